// round 12
// baseline (speedup 1.0000x reference)
#include <cuda_runtime.h>
#include <cuda_fp16.h>
#include <cstdint>
#include <math.h>

#define BB 4
#define SS 2048
#define EE 1024
#define HH 16
#define DD 64
#define TOK (BB * SS)
#define LN_EPS 1e-5f
// SCALE * log2(e): softmax done in exp2 domain
#define QSCALE 0.1803368801111244f

__device__ __half g_xh[(size_t)TOK * EE];            // fp16 copy of X
__device__ __half g_wh[2][(size_t)EE * EE];          // fp16 Wq, Wk
__device__ __half g_qh[(size_t)TOK * EE];
__device__ __half g_kh[(size_t)TOK * EE];
__device__ __half g_vt[(size_t)BB * HH * DD * SS];   // [b][h][d][s]
__device__ float  g_ctx[(size_t)TOK * EE];

// ---------------------------------------------------------------------------
// PTX helpers
// ---------------------------------------------------------------------------
__device__ __forceinline__ uint32_t smem_u32(const void* p) {
    uint32_t a;
    asm("{ .reg .u64 t; cvta.to.shared.u64 t, %1; cvt.u32.u64 %0, t; }"
        : "=r"(a) : "l"(p));
    return a;
}

#define CP_ASYNC16(sa, gp) \
    asm volatile("cp.async.cg.shared.global [%0], [%1], 16;" \
                 :: "r"(sa), "l"(gp))
#define CP_COMMIT() asm volatile("cp.async.commit_group;" ::: "memory")
#define CP_WAIT1()  asm volatile("cp.async.wait_group 1;" ::: "memory")
#define CP_WAIT0()  asm volatile("cp.async.wait_group 0;" ::: "memory")

#define LDSM4(R0, R1, R2, R3, ADDR) \
    asm volatile("ldmatrix.sync.aligned.m8n8.x4.shared.b16 {%0,%1,%2,%3}, [%4];" \
                 : "=r"(R0), "=r"(R1), "=r"(R2), "=r"(R3) : "r"(ADDR))
#define LDSM4T(R0, R1, R2, R3, ADDR) \
    asm volatile("ldmatrix.sync.aligned.m8n8.x4.trans.shared.b16 {%0,%1,%2,%3}, [%4];" \
                 : "=r"(R0), "=r"(R1), "=r"(R2), "=r"(R3) : "r"(ADDR))

// fp32-accumulate mma (GEMM, PV, l)
#define MMA16816(D, A0, A1, A2, A3, B0, B1) \
    asm volatile("mma.sync.aligned.m16n8k16.row.col.f32.f16.f16.f32 " \
                 "{%0,%1,%2,%3}, {%4,%5,%6,%7}, {%8,%9}, {%0,%1,%2,%3};" \
                 : "+f"((D)[0]), "+f"((D)[1]), "+f"((D)[2]), "+f"((D)[3]) \
                 : "r"(A0), "r"(A1), "r"(A2), "r"(A3), "r"(B0), "r"(B1))

// fp16-accumulate mma (attention S): D regs come out in PV A-fragment layout
#define MMA16816_H(D0, D1, A0, A1, A2, A3, B0, B1) \
    asm volatile("mma.sync.aligned.m16n8k16.row.col.f16.f16.f16.f16 " \
                 "{%0,%1}, {%2,%3,%4,%5}, {%6,%7}, {%0,%1};" \
                 : "+r"(D0), "+r"(D1) \
                 : "r"(A0), "r"(A1), "r"(A2), "r"(A3), "r"(B0), "r"(B1))

// exp2 on packed fp16x2, in place
#define EX2H2(R) asm("ex2.approx.f16x2 %0, %0;" : "+r"(R))

#define ONES_H2 0x3C003C00u   // (1.0h, 1.0h)

__device__ __forceinline__ uint32_t pack_h2(float a, float b) {
    __half2 h = __floats2half2_rn(a, b);
    return *reinterpret_cast<uint32_t*>(&h);
}

// ---------------------------------------------------------------------------
// Kernel 0a: X -> g_vt [b][h][d][s] fp16 AND g_xh row-major fp16.
// ---------------------------------------------------------------------------
__global__ __launch_bounds__(256) void vt_kernel(const float* __restrict__ X)
{
    __shared__ float sm[64][65];
    const int tid = threadIdx.x;
    const int bh = blockIdx.y, b = bh >> 4, h = bh & 15;
    const int s0 = blockIdx.x * 64;

#pragma unroll
    for (int r = 0; r < 4; ++r) {
        int idx = tid + r * 256;
        int row = idx >> 4;
        int c4  = (idx & 15) << 2;
        const size_t goff = ((size_t)(b * SS + s0 + row)) * EE + h * DD + c4;
        float4 v = *(const float4*)(X + goff);
        sm[row][c4 + 0] = v.x; sm[row][c4 + 1] = v.y;
        sm[row][c4 + 2] = v.z; sm[row][c4 + 3] = v.w;
        uint2 hx = make_uint2(pack_h2(v.x, v.y), pack_h2(v.z, v.w));
        *reinterpret_cast<uint2*>(g_xh + goff) = hx;
    }
    __syncthreads();
#pragma unroll
    for (int r = 0; r < 8; ++r) {
        int idx = tid + r * 256;
        int d  = idx >> 5;
        int s2 = (idx & 31) * 2;
        __half2 h2 = __floats2half2_rn(sm[s2][d], sm[s2 + 1][d]);
        *reinterpret_cast<__half2*>(g_vt + ((size_t)bh * DD + d) * SS + s0 + s2) = h2;
    }
}

// ---------------------------------------------------------------------------
// Kernel 0b: Wq/Wk -> fp16.
// ---------------------------------------------------------------------------
__global__ __launch_bounds__(256) void wconv_kernel(
    const float* __restrict__ Wq, const float* __restrict__ Wk)
{
    const float* src = (blockIdx.y == 0) ? Wq : Wk;
    __half* dst = g_wh[blockIdx.y];
    const size_t i4 = (size_t)blockIdx.x * 256 + threadIdx.x;
    float4 v = *(const float4*)(src + i4 * 4);
    uint2 hx = make_uint2(pack_h2(v.x, v.y), pack_h2(v.z, v.w));
    *reinterpret_cast<uint2*>(dst + i4 * 4) = hx;
}

// ---------------------------------------------------------------------------
// Kernel 1: fused Q/K projection GEMM, fp16 mma (unchanged).
// ---------------------------------------------------------------------------
#define GA_PITCH 80
#define GB_PITCH 272
#define G_SA(buf) ((buf) * 128 * GA_PITCH)
#define G_SB(buf) (2 * 128 * GA_PITCH + (buf) * 32 * GB_PITCH)
#define G_SMEM_BYTES (2 * 128 * GA_PITCH + 2 * 32 * GB_PITCH)

__global__ __launch_bounds__(256) void gemm_qk_h()
{
    extern __shared__ char smg[];
    const uint32_t sb = smem_u32(smg);

    const __half* Xh = g_xh;
    const __half* Wh = g_wh[blockIdx.z];
    __half* C        = (blockIdx.z == 0) ? g_qh : g_kh;
    const float qsc  = (blockIdx.z == 0) ? QSCALE : 1.0f;

    const int m0 = blockIdx.y * 128;
    const int n0 = blockIdx.x * 128;
    const int tid = threadIdx.x;
    const int wid = tid >> 5;
    const int lane = tid & 31;
    const int gid = lane >> 2;
    const int tig = lane & 3;
    const int wm = (wid >> 1) * 32;
    const int wn = (wid & 1) * 64;

    float acc[2][8][4];
#pragma unroll
    for (int mt = 0; mt < 2; ++mt)
#pragma unroll
        for (int nt = 0; nt < 8; ++nt)
#pragma unroll
            for (int r = 0; r < 4; ++r) acc[mt][nt][r] = 0.f;

#pragma unroll
    for (int i = 0; i < 2; ++i) {
        int idx = tid + i * 256;
        int arow = idx >> 2, aseg = idx & 3;
        CP_ASYNC16(sb + G_SA(0) + arow * GA_PITCH + aseg * 16,
                   Xh + (size_t)(m0 + arow) * EE + aseg * 8);
        int brow = idx >> 4, bseg = idx & 15;
        CP_ASYNC16(sb + G_SB(0) + brow * GB_PITCH + bseg * 16,
                   Wh + (size_t)brow * EE + n0 + bseg * 8);
    }
    CP_COMMIT();

    const uint32_t a_lm = (uint32_t)((lane & 15) * GA_PITCH + ((lane & 16) ? 16 : 0));
    const uint32_t b_lm = (uint32_t)((lane & 15) * GB_PITCH + ((lane & 16) ? 16 : 0));

    for (int ch = 0; ch < 32; ++ch) {
        const int buf = ch & 1;
        if (ch + 1 < 32) {
            const int k0 = (ch + 1) * 32;
            const int nb = buf ^ 1;
#pragma unroll
            for (int i = 0; i < 2; ++i) {
                int idx = tid + i * 256;
                int arow = idx >> 2, aseg = idx & 3;
                CP_ASYNC16(sb + G_SA(nb) + arow * GA_PITCH + aseg * 16,
                           Xh + (size_t)(m0 + arow) * EE + k0 + aseg * 8);
                int brow = idx >> 4, bseg = idx & 15;
                CP_ASYNC16(sb + G_SB(nb) + brow * GB_PITCH + bseg * 16,
                           Wh + (size_t)(k0 + brow) * EE + n0 + bseg * 8);
            }
            CP_COMMIT();
            CP_WAIT1();
        } else {
            CP_WAIT0();
        }
        __syncthreads();

        const uint32_t sa = sb + G_SA(buf);
        const uint32_t sbf = sb + G_SB(buf);

#pragma unroll
        for (int ks = 0; ks < 2; ++ks) {
            uint32_t af[2][4];
#pragma unroll
            for (int mt = 0; mt < 2; ++mt) {
                LDSM4(af[mt][0], af[mt][1], af[mt][2], af[mt][3],
                      sa + (wm + mt * 16) * GA_PITCH + a_lm + ks * 32);
            }
#pragma unroll
            for (int np = 0; np < 4; ++np) {
                uint32_t b0, b1, b2, b3;
                LDSM4T(b0, b1, b2, b3,
                       sbf + ks * 16 * GB_PITCH + b_lm + (wn + np * 16) * 2);
                MMA16816(acc[0][2 * np + 0], af[0][0], af[0][1], af[0][2], af[0][3], b0, b1);
                MMA16816(acc[0][2 * np + 1], af[0][0], af[0][1], af[0][2], af[0][3], b2, b3);
                MMA16816(acc[1][2 * np + 0], af[1][0], af[1][1], af[1][2], af[1][3], b0, b1);
                MMA16816(acc[1][2 * np + 1], af[1][0], af[1][1], af[1][2], af[1][3], b2, b3);
            }
        }
        __syncthreads();
    }

#pragma unroll
    for (int mt = 0; mt < 2; ++mt) {
        const int r0 = m0 + wm + mt * 16 + gid;
#pragma unroll
        for (int nt = 0; nt < 8; ++nt) {
            const int ncol = n0 + wn + nt * 8 + tig * 2;
            __half2 h0 = __floats2half2_rn(acc[mt][nt][0] * qsc, acc[mt][nt][1] * qsc);
            __half2 h1 = __floats2half2_rn(acc[mt][nt][2] * qsc, acc[mt][nt][3] * qsc);
            *reinterpret_cast<__half2*>(C + (size_t)(r0 + 0) * EE + ncol) = h0;
            *reinterpret_cast<__half2*>(C + (size_t)(r0 + 8) * EE + ncol) = h1;
        }
    }
}

// ---------------------------------------------------------------------------
// Kernel 2: flash attention. 256-query CTA tile; each warp owns 32 query
// rows (2 m16 tiles) so every K/V fragment feeds 2x the mma work -> LDSM
// bytes per FLOP halved. fp16-D S-mma, exp2 in place, l via ones-mma.
// smem: Q 256x144B @0; K[2] 128x144B @36864; V[2] 64x272B @73728. (106KB)
// ---------------------------------------------------------------------------
#define AT_OQ    0
#define AT_OK    36864
#define AT_KBUF  18432
#define AT_OV    (36864 + 2 * 18432)        // 73728
#define AT_VBUF  17408
#define AT_SMEM_BYTES (AT_OV + 2 * AT_VBUF) // 108544

__global__ __launch_bounds__(256, 2) void attn_h()
{
    extern __shared__ char sma[];
    const uint32_t sb = smem_u32(sma);
    const int tid = threadIdx.x;
    const int wid = tid >> 5, lane = tid & 31;
    const int gid = lane >> 2, tig = lane & 3;
    const int wm = wid * 32;                 // 32 query rows per warp
    const int bh = blockIdx.y, b = bh >> 4, h = bh & 15;
    const int s0 = blockIdx.x * 256;

    const __half* qsrc = g_qh + ((size_t)(b * SS + s0)) * EE + h * DD;
    const __half* ksrc = g_kh + ((size_t)b * SS) * EE + h * DD;
    const __half* vsrc = g_vt + ((size_t)bh * DD) * SS;

    // Stage Q (256 rows x 64h).
#pragma unroll
    for (int r = 0; r < 8; ++r) {
        int idx = tid + r * 256;
        int row = idx >> 3, seg = idx & 7;
        CP_ASYNC16(sb + AT_OQ + row * 144 + seg * 16,
                   qsrc + (size_t)row * EE + seg * 8);
    }
    // Tile 0 of K (128 keys x 64h) and V (64d x 128 keys).
#pragma unroll
    for (int r = 0; r < 4; ++r) {
        int idx = tid + r * 256;
        int krow = idx >> 3, kseg = idx & 7;
        CP_ASYNC16(sb + AT_OK + krow * 144 + kseg * 16,
                   ksrc + (size_t)krow * EE + kseg * 8);
        int vrow = idx >> 4, vseg = idx & 15;
        CP_ASYNC16(sb + AT_OV + vrow * 272 + vseg * 16,
                   vsrc + (size_t)vrow * SS + vseg * 8);
    }
    CP_COMMIT();
    CP_WAIT0();
    __syncthreads();

    // Q fragments for both m16 tiles: persistent (32 regs).
    uint32_t qf[2][4][4];
#pragma unroll
    for (int mt = 0; mt < 2; ++mt) {
        const uint32_t qoff = sb + AT_OQ
            + (uint32_t)(wm + mt * 16 + (lane & 15)) * 144
            + ((lane & 16) ? 16u : 0u);
#pragma unroll
        for (int ks = 0; ks < 4; ++ks)
            LDSM4(qf[mt][ks][0], qf[mt][ks][1], qf[mt][ks][2], qf[mt][ks][3],
                  qoff + 32 * ks);
    }

    float oacc[2][8][4];
#pragma unroll
    for (int mt = 0; mt < 2; ++mt)
#pragma unroll
        for (int nt = 0; nt < 8; ++nt)
#pragma unroll
            for (int r = 0; r < 4; ++r) oacc[mt][nt][r] = 0.f;
    float lacc[2][4];
#pragma unroll
    for (int mt = 0; mt < 2; ++mt)
#pragma unroll
        for (int r = 0; r < 4; ++r) lacc[mt][r] = 0.f;

    const uint32_t kmoff = (uint32_t)((lane & 7) * 144 + (lane >> 3) * 16);
    const uint32_t vmoff = (uint32_t)((lane & 7) * 272 + (lane >> 3) * 16);

    for (int kt = 0; kt < 16; ++kt) {
        const int buf = kt & 1;
        if (kt + 1 < 16) {
            const int t0n = (kt + 1) * 128;
            const int nb = buf ^ 1;
#pragma unroll
            for (int r = 0; r < 4; ++r) {
                int idx = tid + r * 256;
                int krow = idx >> 3, kseg = idx & 7;
                CP_ASYNC16(sb + AT_OK + nb * AT_KBUF + krow * 144 + kseg * 16,
                           ksrc + (size_t)(t0n + krow) * EE + kseg * 8);
                int vrow = idx >> 4, vseg = idx & 15;
                CP_ASYNC16(sb + AT_OV + nb * AT_VBUF + vrow * 272 + vseg * 16,
                           vsrc + (size_t)vrow * SS + t0n + vseg * 8);
            }
            CP_COMMIT();
            CP_WAIT1();
        } else {
            CP_WAIT0();
        }
        __syncthreads();

        const uint32_t kb = sb + AT_OK + buf * AT_KBUF + kmoff;
        const uint32_t vb = sb + AT_OV + buf * AT_VBUF + vmoff;

        // ---- per 32-key chunk: S(both m) -> exp2 -> l -> PV(both m) ----
#pragma unroll
        for (int c = 0; c < 4; ++c) {
            uint32_t sh[2][4][2];
#pragma unroll
            for (int mt = 0; mt < 2; ++mt)
#pragma unroll
                for (int nt = 0; nt < 4; ++nt) { sh[mt][nt][0] = 0u; sh[mt][nt][1] = 0u; }

            // S: K fragment loaded once, used by BOTH m16 tiles.
#pragma unroll
            for (int nt = 0; nt < 4; ++nt) {
                const int ntg = c * 4 + nt;
                uint32_t k0, k1, k2, k3, k4, k5, k6, k7;
                LDSM4(k0, k1, k2, k3, kb + ntg * 1152);
                LDSM4(k4, k5, k6, k7, kb + ntg * 1152 + 64);
#pragma unroll
                for (int mt = 0; mt < 2; ++mt) {
                    MMA16816_H(sh[mt][nt][0], sh[mt][nt][1],
                               qf[mt][0][0], qf[mt][0][1], qf[mt][0][2], qf[mt][0][3], k0, k1);
                    MMA16816_H(sh[mt][nt][0], sh[mt][nt][1],
                               qf[mt][1][0], qf[mt][1][1], qf[mt][1][2], qf[mt][1][3], k2, k3);
                    MMA16816_H(sh[mt][nt][0], sh[mt][nt][1],
                               qf[mt][2][0], qf[mt][2][1], qf[mt][2][2], qf[mt][2][3], k4, k5);
                    MMA16816_H(sh[mt][nt][0], sh[mt][nt][1],
                               qf[mt][3][0], qf[mt][3][1], qf[mt][3][2], qf[mt][3][3], k6, k7);
                }
            }

            // P = exp2(S) in place; sh pairs are PV A-fragments.
#pragma unroll
            for (int mt = 0; mt < 2; ++mt)
#pragma unroll
                for (int nt = 0; nt < 4; ++nt) { EX2H2(sh[mt][nt][0]); EX2H2(sh[mt][nt][1]); }

            // l += P @ ones
#pragma unroll
            for (int mt = 0; mt < 2; ++mt) {
                MMA16816(lacc[mt], sh[mt][0][0], sh[mt][0][1], sh[mt][1][0], sh[mt][1][1],
                         ONES_H2, ONES_H2);
                MMA16816(lacc[mt], sh[mt][2][0], sh[mt][2][1], sh[mt][3][0], sh[mt][3][1],
                         ONES_H2, ONES_H2);
            }

            // PV: V fragment loaded once, used by BOTH m16 tiles.
#pragma unroll
            for (int dt = 0; dt < 8; ++dt) {
                uint32_t v0, v1, v2, v3;
                LDSM4(v0, v1, v2, v3, vb + dt * 2176 + c * 64);
#pragma unroll
                for (int mt = 0; mt < 2; ++mt) {
                    MMA16816(oacc[mt][dt], sh[mt][0][0], sh[mt][0][1], sh[mt][1][0], sh[mt][1][1],
                             v0, v1);
                    MMA16816(oacc[mt][dt], sh[mt][2][0], sh[mt][2][1], sh[mt][3][0], sh[mt][3][1],
                             v2, v3);
                }
            }
        }
        __syncthreads();
    }

    // Epilogue: normalize and write both m16 tiles.
#pragma unroll
    for (int mt = 0; mt < 2; ++mt) {
        const float li0 = 1.0f / lacc[mt][0];
        const float li1 = 1.0f / lacc[mt][2];
        float* op = g_ctx + ((size_t)(b * SS + s0 + wm + mt * 16 + gid)) * EE + h * DD;
#pragma unroll
        for (int dt = 0; dt < 8; ++dt) {
            const int dcol = dt * 8 + tig * 2;
            float2 v0 = make_float2(oacc[mt][dt][0] * li0, oacc[mt][dt][1] * li0);
            float2 v1 = make_float2(oacc[mt][dt][2] * li1, oacc[mt][dt][3] * li1);
            *(float2*)(op + dcol) = v0;
            *(float2*)(op + (size_t)8 * EE + dcol) = v1;
        }
    }
}

// ---------------------------------------------------------------------------
// Kernel 3: residual + LayerNorm (unchanged).
// ---------------------------------------------------------------------------
__global__ __launch_bounds__(256) void ln_kernel(
    const float* __restrict__ X,
    const float* __restrict__ w,
    const float* __restrict__ bias,
    float* __restrict__ out)
{
    const int token = blockIdx.x;
    const int tid = threadIdx.x;
    const float* cp = g_ctx + (size_t)token * EE;
    const float* xp = X + (size_t)token * EE;

    float4 c  = *(const float4*)(cp + tid * 4);
    float4 xv = *(const float4*)(xp + tid * 4);
    float y0 = c.x + xv.x, y1 = c.y + xv.y, y2 = c.z + xv.z, y3 = c.w + xv.w;

    float sum = y0 + y1 + y2 + y3;
    float sq  = y0 * y0 + y1 * y1 + y2 * y2 + y3 * y3;
#pragma unroll
    for (int off = 16; off > 0; off >>= 1) {
        sum += __shfl_xor_sync(0xffffffffu, sum, off);
        sq  += __shfl_xor_sync(0xffffffffu, sq,  off);
    }
    __shared__ float ws[8], wq[8];
    __shared__ float s_mu, s_rinv;
    const int lane = tid & 31, wrp = tid >> 5;
    if (lane == 0) { ws[wrp] = sum; wq[wrp] = sq; }
    __syncthreads();
    if (tid < 32) {
        float a  = (tid < 8) ? ws[tid] : 0.f;
        float b2 = (tid < 8) ? wq[tid] : 0.f;
#pragma unroll
        for (int off = 4; off > 0; off >>= 1) {
            a  += __shfl_xor_sync(0xffffffffu, a, off);
            b2 += __shfl_xor_sync(0xffffffffu, b2, off);
        }
        if (tid == 0) {
            float mu  = a * (1.0f / EE);
            float var = b2 * (1.0f / EE) - mu * mu;
            s_mu = mu;
            s_rinv = rsqrtf(var + LN_EPS);
        }
    }
    __syncthreads();
    const float mu = s_mu, rinv = s_rinv;
    float4 w4 = *(const float4*)(w + tid * 4);
    float4 b4 = *(const float4*)(bias + tid * 4);
    float4 o;
    o.x = (y0 - mu) * rinv * w4.x + b4.x;
    o.y = (y1 - mu) * rinv * w4.y + b4.y;
    o.z = (y2 - mu) * rinv * w4.z + b4.z;
    o.w = (y3 - mu) * rinv * w4.w + b4.w;
    *(float4*)(out + (size_t)token * EE + tid * 4) = o;
}

// ---------------------------------------------------------------------------
extern "C" void kernel_launch(void* const* d_in, const int* in_sizes, int n_in,
                              void* d_out, int out_size)
{
    const float* Wq = (const float*)d_in[0];
    const float* Wk = (const float*)d_in[1];
    const float* X  = (const float*)d_in[2];
    const float* lw = (const float*)d_in[3];
    const float* lb = (const float*)d_in[4];
    float* out = (float*)d_out;

    cudaFuncSetAttribute(gemm_qk_h,
                         cudaFuncAttributeMaxDynamicSharedMemorySize,
                         G_SMEM_BYTES);
    cudaFuncSetAttribute(attn_h,
                         cudaFuncAttributeMaxDynamicSharedMemorySize,
                         AT_SMEM_BYTES);

    wconv_kernel<<<dim3(1024, 2), 256>>>(Wq, Wk);
    vt_kernel<<<dim3(32, 64), 256>>>(X);
    gemm_qk_h<<<dim3(8, 64, 2), 256, G_SMEM_BYTES>>>();
    attn_h<<<dim3(8, 64), 256, AT_SMEM_BYTES>>>();
    ln_kernel<<<dim3(TOK), 256>>>(X, lw, lb, out);
}

// round 13
// speedup vs baseline: 1.0182x; 1.0182x over previous
#include <cuda_runtime.h>
#include <cuda_fp16.h>
#include <cstdint>
#include <math.h>

#define BB 4
#define SS 2048
#define EE 1024
#define HH 16
#define DD 64
#define TOK (BB * SS)
#define LN_EPS 1e-5f
// SCALE * log2(e): softmax done in exp2 domain
#define QSCALE 0.1803368801111244f

__device__ __half g_xh[(size_t)TOK * EE];            // fp16 copy of X
__device__ __half g_wh[2][(size_t)EE * EE];          // fp16 Wq, Wk
__device__ __half g_qh[(size_t)TOK * EE];
__device__ __half g_kh[(size_t)TOK * EE];
__device__ __half g_vt[(size_t)BB * HH * DD * SS];   // [b][h][d][s]
__device__ float  g_ctx[(size_t)TOK * EE];

// ---------------------------------------------------------------------------
// PTX helpers
// ---------------------------------------------------------------------------
__device__ __forceinline__ uint32_t smem_u32(const void* p) {
    uint32_t a;
    asm("{ .reg .u64 t; cvta.to.shared.u64 t, %1; cvt.u32.u64 %0, t; }"
        : "=r"(a) : "l"(p));
    return a;
}

#define CP_ASYNC16(sa, gp) \
    asm volatile("cp.async.cg.shared.global [%0], [%1], 16;" \
                 :: "r"(sa), "l"(gp))
#define CP_COMMIT() asm volatile("cp.async.commit_group;" ::: "memory")
#define CP_WAIT1()  asm volatile("cp.async.wait_group 1;" ::: "memory")
#define CP_WAIT0()  asm volatile("cp.async.wait_group 0;" ::: "memory")

#define LDSM4(R0, R1, R2, R3, ADDR) \
    asm volatile("ldmatrix.sync.aligned.m8n8.x4.shared.b16 {%0,%1,%2,%3}, [%4];" \
                 : "=r"(R0), "=r"(R1), "=r"(R2), "=r"(R3) : "r"(ADDR))
#define LDSM4T(R0, R1, R2, R3, ADDR) \
    asm volatile("ldmatrix.sync.aligned.m8n8.x4.trans.shared.b16 {%0,%1,%2,%3}, [%4];" \
                 : "=r"(R0), "=r"(R1), "=r"(R2), "=r"(R3) : "r"(ADDR))

// fp32-accumulate mma (GEMM, PV, l)
#define MMA16816(D, A0, A1, A2, A3, B0, B1) \
    asm volatile("mma.sync.aligned.m16n8k16.row.col.f32.f16.f16.f32 " \
                 "{%0,%1,%2,%3}, {%4,%5,%6,%7}, {%8,%9}, {%0,%1,%2,%3};" \
                 : "+f"((D)[0]), "+f"((D)[1]), "+f"((D)[2]), "+f"((D)[3]) \
                 : "r"(A0), "r"(A1), "r"(A2), "r"(A3), "r"(B0), "r"(B1))

// fp16-accumulate mma (attention S): D regs come out in PV A-fragment layout
#define MMA16816_H(D0, D1, A0, A1, A2, A3, B0, B1) \
    asm volatile("mma.sync.aligned.m16n8k16.row.col.f16.f16.f16.f16 " \
                 "{%0,%1}, {%2,%3,%4,%5}, {%6,%7}, {%0,%1};" \
                 : "+r"(D0), "+r"(D1) \
                 : "r"(A0), "r"(A1), "r"(A2), "r"(A3), "r"(B0), "r"(B1))

// exp2 on packed fp16x2, in place
#define EX2H2(R) asm("ex2.approx.f16x2 %0, %0;" : "+r"(R))

#define ONES_H2 0x3C003C00u   // (1.0h, 1.0h)

__device__ __forceinline__ uint32_t pack_h2(float a, float b) {
    __half2 h = __floats2half2_rn(a, b);
    return *reinterpret_cast<uint32_t*>(&h);
}

// ---------------------------------------------------------------------------
// Kernel 0a: X -> g_vt [b][h][d][s] fp16 AND g_xh row-major fp16.
// ---------------------------------------------------------------------------
__global__ __launch_bounds__(256) void vt_kernel(const float* __restrict__ X)
{
    __shared__ float sm[64][65];
    const int tid = threadIdx.x;
    const int bh = blockIdx.y, b = bh >> 4, h = bh & 15;
    const int s0 = blockIdx.x * 64;

#pragma unroll
    for (int r = 0; r < 4; ++r) {
        int idx = tid + r * 256;
        int row = idx >> 4;
        int c4  = (idx & 15) << 2;
        const size_t goff = ((size_t)(b * SS + s0 + row)) * EE + h * DD + c4;
        float4 v = *(const float4*)(X + goff);
        sm[row][c4 + 0] = v.x; sm[row][c4 + 1] = v.y;
        sm[row][c4 + 2] = v.z; sm[row][c4 + 3] = v.w;
        uint2 hx = make_uint2(pack_h2(v.x, v.y), pack_h2(v.z, v.w));
        *reinterpret_cast<uint2*>(g_xh + goff) = hx;
    }
    __syncthreads();
#pragma unroll
    for (int r = 0; r < 8; ++r) {
        int idx = tid + r * 256;
        int d  = idx >> 5;
        int s2 = (idx & 31) * 2;
        __half2 h2 = __floats2half2_rn(sm[s2][d], sm[s2 + 1][d]);
        *reinterpret_cast<__half2*>(g_vt + ((size_t)bh * DD + d) * SS + s0 + s2) = h2;
    }
}

// ---------------------------------------------------------------------------
// Kernel 0b: Wq/Wk -> fp16.
// ---------------------------------------------------------------------------
__global__ __launch_bounds__(256) void wconv_kernel(
    const float* __restrict__ Wq, const float* __restrict__ Wk)
{
    const float* src = (blockIdx.y == 0) ? Wq : Wk;
    __half* dst = g_wh[blockIdx.y];
    const size_t i4 = (size_t)blockIdx.x * 256 + threadIdx.x;
    float4 v = *(const float4*)(src + i4 * 4);
    uint2 hx = make_uint2(pack_h2(v.x, v.y), pack_h2(v.z, v.w));
    *reinterpret_cast<uint2*>(dst + i4 * 4) = hx;
}

// ---------------------------------------------------------------------------
// Kernel 1: FUSED Q+K projection GEMM. One CTA computes BOTH Q and K for
// its 128x128 tile, sharing a single A (X) smem buffer -> A L2 traffic
// halved. 512 thr = 16 warps: warps 0-7 -> Wq, warps 8-15 -> Wk.
// grid (8, 64). smem: A[2] 128x80B @0; B[wz][2] 32x272B @20480.
// ---------------------------------------------------------------------------
#define GA_PITCH 80
#define GB_PITCH 272
#define FG_SA(buf)      ((buf) * 10240)
#define FG_SB(wz, buf)  (20480 + (wz) * 17408 + (buf) * 8704)
#define FG_SMEM_BYTES   (20480 + 2 * 17408)   // 55296

__global__ __launch_bounds__(512) void gemm_qk_h()
{
    extern __shared__ char smg[];
    const uint32_t sb = smem_u32(smg);

    const __half* Xh = g_xh;

    const int m0 = blockIdx.y * 128;
    const int n0 = blockIdx.x * 128;
    const int tid = threadIdx.x;
    const int wid = tid >> 5;
    const int lane = tid & 31;
    const int gid = lane >> 2;
    const int tig = lane & 3;
    const int wz = wid >> 3;                 // 0 -> Q, 1 -> K
    const int w8 = wid & 7;
    const int wm = (w8 >> 1) * 32;
    const int wn = (w8 & 1) * 64;

    const __half* Wh = g_wh[wz];
    __half* C        = (wz == 0) ? g_qh : g_kh;
    const float qsc  = (wz == 0) ? QSCALE : 1.0f;

    float acc[2][8][4];
#pragma unroll
    for (int mt = 0; mt < 2; ++mt)
#pragma unroll
        for (int nt = 0; nt < 8; ++nt)
#pragma unroll
            for (int r = 0; r < 4; ++r) acc[mt][nt][r] = 0.f;

    // Prefetch chunk 0: A (128x32h = 512x16B), Bq + Bk (each 32x128h = 512x16B).
    {
        int arow = tid >> 2, aseg = tid & 3;
        CP_ASYNC16(sb + FG_SA(0) + arow * GA_PITCH + aseg * 16,
                   Xh + (size_t)(m0 + arow) * EE + aseg * 8);
        int brow = tid >> 4, bseg = tid & 15;
        CP_ASYNC16(sb + FG_SB(0, 0) + brow * GB_PITCH + bseg * 16,
                   g_wh[0] + (size_t)brow * EE + n0 + bseg * 8);
        CP_ASYNC16(sb + FG_SB(1, 0) + brow * GB_PITCH + bseg * 16,
                   g_wh[1] + (size_t)brow * EE + n0 + bseg * 8);
    }
    CP_COMMIT();

    const uint32_t a_lm = (uint32_t)((lane & 15) * GA_PITCH + ((lane & 16) ? 16 : 0));
    const uint32_t b_lm = (uint32_t)((lane & 15) * GB_PITCH + ((lane & 16) ? 16 : 0));

    for (int ch = 0; ch < 32; ++ch) {
        const int buf = ch & 1;
        if (ch + 1 < 32) {
            const int k0 = (ch + 1) * 32;
            const int nb = buf ^ 1;
            int arow = tid >> 2, aseg = tid & 3;
            CP_ASYNC16(sb + FG_SA(nb) + arow * GA_PITCH + aseg * 16,
                       Xh + (size_t)(m0 + arow) * EE + k0 + aseg * 8);
            int brow = tid >> 4, bseg = tid & 15;
            CP_ASYNC16(sb + FG_SB(0, nb) + brow * GB_PITCH + bseg * 16,
                       g_wh[0] + (size_t)(k0 + brow) * EE + n0 + bseg * 8);
            CP_ASYNC16(sb + FG_SB(1, nb) + brow * GB_PITCH + bseg * 16,
                       g_wh[1] + (size_t)(k0 + brow) * EE + n0 + bseg * 8);
            CP_COMMIT();
            CP_WAIT1();
        } else {
            CP_WAIT0();
        }
        __syncthreads();

        const uint32_t sa  = sb + FG_SA(buf);
        const uint32_t sbf = sb + FG_SB(wz, buf);

#pragma unroll
        for (int ks = 0; ks < 2; ++ks) {
            uint32_t af[2][4];
#pragma unroll
            for (int mt = 0; mt < 2; ++mt) {
                LDSM4(af[mt][0], af[mt][1], af[mt][2], af[mt][3],
                      sa + (wm + mt * 16) * GA_PITCH + a_lm + ks * 32);
            }
#pragma unroll
            for (int np = 0; np < 4; ++np) {
                uint32_t b0, b1, b2, b3;
                LDSM4T(b0, b1, b2, b3,
                       sbf + ks * 16 * GB_PITCH + b_lm + (wn + np * 16) * 2);
                MMA16816(acc[0][2 * np + 0], af[0][0], af[0][1], af[0][2], af[0][3], b0, b1);
                MMA16816(acc[0][2 * np + 1], af[0][0], af[0][1], af[0][2], af[0][3], b2, b3);
                MMA16816(acc[1][2 * np + 0], af[1][0], af[1][1], af[1][2], af[1][3], b0, b1);
                MMA16816(acc[1][2 * np + 1], af[1][0], af[1][1], af[1][2], af[1][3], b2, b3);
            }
        }
        __syncthreads();
    }

#pragma unroll
    for (int mt = 0; mt < 2; ++mt) {
        const int r0 = m0 + wm + mt * 16 + gid;
#pragma unroll
        for (int nt = 0; nt < 8; ++nt) {
            const int ncol = n0 + wn + nt * 8 + tig * 2;
            __half2 h0 = __floats2half2_rn(acc[mt][nt][0] * qsc, acc[mt][nt][1] * qsc);
            __half2 h1 = __floats2half2_rn(acc[mt][nt][2] * qsc, acc[mt][nt][3] * qsc);
            *reinterpret_cast<__half2*>(C + (size_t)(r0 + 0) * EE + ncol) = h0;
            *reinterpret_cast<__half2*>(C + (size_t)(r0 + 8) * EE + ncol) = h1;
        }
    }
}

// ---------------------------------------------------------------------------
// Kernel 2: flash attention (round-11 winner, verbatim). 128-query x 128-key
// tiles, fp16-D S-mma whose output registers ARE the PV A-fragments.
// smem: Q 128x144B @0; K[2] 128x144B @18432; V[2] 64x272B @55296.
// ---------------------------------------------------------------------------
#define AT_OQ    0
#define AT_OK    18432
#define AT_KBUF  18432
#define AT_OV    (18432 + 2 * 18432)        // 55296
#define AT_VBUF  17408
#define AT_SMEM_BYTES (AT_OV + 2 * AT_VBUF) // 90112

__global__ __launch_bounds__(256, 2) void attn_h()
{
    extern __shared__ char sma[];
    const uint32_t sb = smem_u32(sma);
    const int tid = threadIdx.x;
    const int wid = tid >> 5, lane = tid & 31;
    const int gid = lane >> 2, tig = lane & 3;
    const int wm = wid * 16;
    const int bh = blockIdx.y, b = bh >> 4, h = bh & 15;
    const int s0 = blockIdx.x * 128;

    const __half* qsrc = g_qh + ((size_t)(b * SS + s0)) * EE + h * DD;
    const __half* ksrc = g_kh + ((size_t)b * SS) * EE + h * DD;
    const __half* vsrc = g_vt + ((size_t)bh * DD) * SS;

    // Stage Q (128 rows x 64h) and tile 0 of K (128 keys) / V (64d x 128keys).
#pragma unroll
    for (int r = 0; r < 4; ++r) {
        int idx = tid + r * 256;
        int row = idx >> 3, seg = idx & 7;
        CP_ASYNC16(sb + AT_OQ + row * 144 + seg * 16,
                   qsrc + (size_t)row * EE + seg * 8);
    }
#pragma unroll
    for (int r = 0; r < 4; ++r) {
        int idx = tid + r * 256;
        int krow = idx >> 3, kseg = idx & 7;
        CP_ASYNC16(sb + AT_OK + krow * 144 + kseg * 16,
                   ksrc + (size_t)krow * EE + kseg * 8);
        int vrow = idx >> 4, vseg = idx & 15;
        CP_ASYNC16(sb + AT_OV + vrow * 272 + vseg * 16,
                   vsrc + (size_t)vrow * SS + vseg * 8);
    }
    CP_COMMIT();
    CP_WAIT0();
    __syncthreads();

    uint32_t qf[4][4];
    {
        const uint32_t qoff = sb + AT_OQ + (uint32_t)(wm + (lane & 15)) * 144
                              + ((lane & 16) ? 16u : 0u);
#pragma unroll
        for (int ks = 0; ks < 4; ++ks)
            LDSM4(qf[ks][0], qf[ks][1], qf[ks][2], qf[ks][3], qoff + 32 * ks);
    }

    float oacc[8][4];
#pragma unroll
    for (int nt = 0; nt < 8; ++nt)
#pragma unroll
        for (int r = 0; r < 4; ++r) oacc[nt][r] = 0.f;
    float lacc[4]  = {0.f, 0.f, 0.f, 0.f};
    float lacc2[4] = {0.f, 0.f, 0.f, 0.f};

    const uint32_t kmoff = (uint32_t)((lane & 7) * 144 + (lane >> 3) * 16);
    const uint32_t vmoff = (uint32_t)((lane & 7) * 272 + (lane >> 3) * 16);

    for (int kt = 0; kt < 16; ++kt) {
        const int buf = kt & 1;
        if (kt + 1 < 16) {
            const int t0n = (kt + 1) * 128;
            const int nb = buf ^ 1;
#pragma unroll
            for (int r = 0; r < 4; ++r) {
                int idx = tid + r * 256;
                int krow = idx >> 3, kseg = idx & 7;
                CP_ASYNC16(sb + AT_OK + nb * AT_KBUF + krow * 144 + kseg * 16,
                           ksrc + (size_t)(t0n + krow) * EE + kseg * 8);
                int vrow = idx >> 4, vseg = idx & 15;
                CP_ASYNC16(sb + AT_OV + nb * AT_VBUF + vrow * 272 + vseg * 16,
                           vsrc + (size_t)vrow * SS + t0n + vseg * 8);
            }
            CP_COMMIT();
            CP_WAIT1();
        } else {
            CP_WAIT0();
        }
        __syncthreads();

        const uint32_t kb = sb + AT_OK + buf * AT_KBUF + kmoff;
        const uint32_t vb = sb + AT_OV + buf * AT_VBUF + vmoff;

        // ---- per 32-key chunk: S (fp16 D) -> exp2 in place -> l -> PV ----
#pragma unroll
        for (int c = 0; c < 4; ++c) {
            uint32_t sh[4][2];
#pragma unroll
            for (int nt = 0; nt < 4; ++nt) { sh[nt][0] = 0u; sh[nt][1] = 0u; }

#pragma unroll
            for (int nt = 0; nt < 4; ++nt) {
                const int ntg = c * 4 + nt;
                uint32_t k0, k1, k2, k3, k4, k5, k6, k7;
                LDSM4(k0, k1, k2, k3, kb + ntg * 1152);
                LDSM4(k4, k5, k6, k7, kb + ntg * 1152 + 64);
                MMA16816_H(sh[nt][0], sh[nt][1], qf[0][0], qf[0][1], qf[0][2], qf[0][3], k0, k1);
                MMA16816_H(sh[nt][0], sh[nt][1], qf[1][0], qf[1][1], qf[1][2], qf[1][3], k2, k3);
                MMA16816_H(sh[nt][0], sh[nt][1], qf[2][0], qf[2][1], qf[2][2], qf[2][3], k4, k5);
                MMA16816_H(sh[nt][0], sh[nt][1], qf[3][0], qf[3][1], qf[3][2], qf[3][3], k6, k7);
            }

#pragma unroll
            for (int nt = 0; nt < 4; ++nt) { EX2H2(sh[nt][0]); EX2H2(sh[nt][1]); }

            MMA16816(lacc,  sh[0][0], sh[0][1], sh[1][0], sh[1][1], ONES_H2, ONES_H2);
            MMA16816(lacc2, sh[2][0], sh[2][1], sh[3][0], sh[3][1], ONES_H2, ONES_H2);

#pragma unroll
            for (int nt = 0; nt < 8; ++nt) {
                uint32_t v0, v1, v2, v3;
                LDSM4(v0, v1, v2, v3, vb + nt * 2176 + c * 64);
                MMA16816(oacc[nt], sh[0][0], sh[0][1], sh[1][0], sh[1][1], v0, v1);
                MMA16816(oacc[nt], sh[2][0], sh[2][1], sh[3][0], sh[3][1], v2, v3);
            }
        }
        __syncthreads();
    }

    const float li0 = 1.0f / (lacc[0] + lacc2[0]);
    const float li1 = 1.0f / (lacc[2] + lacc2[2]);

    float* op = g_ctx + ((size_t)(b * SS + s0 + wm + gid)) * EE + h * DD;
#pragma unroll
    for (int nt = 0; nt < 8; ++nt) {
        const int dcol = nt * 8 + tig * 2;
        float2 v0 = make_float2(oacc[nt][0] * li0, oacc[nt][1] * li0);
        float2 v1 = make_float2(oacc[nt][2] * li1, oacc[nt][3] * li1);
        *(float2*)(op + dcol) = v0;
        *(float2*)(op + (size_t)8 * EE + dcol) = v1;
    }
}

// ---------------------------------------------------------------------------
// Kernel 3: residual + LayerNorm (unchanged).
// ---------------------------------------------------------------------------
__global__ __launch_bounds__(256) void ln_kernel(
    const float* __restrict__ X,
    const float* __restrict__ w,
    const float* __restrict__ bias,
    float* __restrict__ out)
{
    const int token = blockIdx.x;
    const int tid = threadIdx.x;
    const float* cp = g_ctx + (size_t)token * EE;
    const float* xp = X + (size_t)token * EE;

    float4 c  = *(const float4*)(cp + tid * 4);
    float4 xv = *(const float4*)(xp + tid * 4);
    float y0 = c.x + xv.x, y1 = c.y + xv.y, y2 = c.z + xv.z, y3 = c.w + xv.w;

    float sum = y0 + y1 + y2 + y3;
    float sq  = y0 * y0 + y1 * y1 + y2 * y2 + y3 * y3;
#pragma unroll
    for (int off = 16; off > 0; off >>= 1) {
        sum += __shfl_xor_sync(0xffffffffu, sum, off);
        sq  += __shfl_xor_sync(0xffffffffu, sq,  off);
    }
    __shared__ float ws[8], wq[8];
    __shared__ float s_mu, s_rinv;
    const int lane = tid & 31, wrp = tid >> 5;
    if (lane == 0) { ws[wrp] = sum; wq[wrp] = sq; }
    __syncthreads();
    if (tid < 32) {
        float a  = (tid < 8) ? ws[tid] : 0.f;
        float b2 = (tid < 8) ? wq[tid] : 0.f;
#pragma unroll
        for (int off = 4; off > 0; off >>= 1) {
            a  += __shfl_xor_sync(0xffffffffu, a, off);
            b2 += __shfl_xor_sync(0xffffffffu, b2, off);
        }
        if (tid == 0) {
            float mu  = a * (1.0f / EE);
            float var = b2 * (1.0f / EE) - mu * mu;
            s_mu = mu;
            s_rinv = rsqrtf(var + LN_EPS);
        }
    }
    __syncthreads();
    const float mu = s_mu, rinv = s_rinv;
    float4 w4 = *(const float4*)(w + tid * 4);
    float4 b4 = *(const float4*)(bias + tid * 4);
    float4 o;
    o.x = (y0 - mu) * rinv * w4.x + b4.x;
    o.y = (y1 - mu) * rinv * w4.y + b4.y;
    o.z = (y2 - mu) * rinv * w4.z + b4.z;
    o.w = (y3 - mu) * rinv * w4.w + b4.w;
    *(float4*)(out + (size_t)token * EE + tid * 4) = o;
}

// ---------------------------------------------------------------------------
extern "C" void kernel_launch(void* const* d_in, const int* in_sizes, int n_in,
                              void* d_out, int out_size)
{
    const float* Wq = (const float*)d_in[0];
    const float* Wk = (const float*)d_in[1];
    const float* X  = (const float*)d_in[2];
    const float* lw = (const float*)d_in[3];
    const float* lb = (const float*)d_in[4];
    float* out = (float*)d_out;

    cudaFuncSetAttribute(gemm_qk_h,
                         cudaFuncAttributeMaxDynamicSharedMemorySize,
                         FG_SMEM_BYTES);
    cudaFuncSetAttribute(attn_h,
                         cudaFuncAttributeMaxDynamicSharedMemorySize,
                         AT_SMEM_BYTES);

    wconv_kernel<<<dim3(1024, 2), 256>>>(Wq, Wk);
    vt_kernel<<<dim3(32, 64), 256>>>(X);
    gemm_qk_h<<<dim3(8, 64), 512, FG_SMEM_BYTES>>>();
    attn_h<<<dim3(16, 64), 256, AT_SMEM_BYTES>>>();
    ln_kernel<<<dim3(TOK), 256>>>(X, lw, lb, out);
}

// round 14
// speedup vs baseline: 1.0513x; 1.0325x over previous
#include <cuda_runtime.h>
#include <cuda_fp16.h>
#include <cstdint>
#include <math.h>

#define BB 4
#define SS 2048
#define EE 1024
#define HH 16
#define DD 64
#define TOK (BB * SS)
#define LN_EPS 1e-5f
// SCALE * log2(e): softmax done in exp2 domain
#define QSCALE 0.1803368801111244f

__device__ __half g_xh[(size_t)TOK * EE];            // fp16 copy of X
__device__ __half g_wh[2][(size_t)EE * EE];          // fp16 Wq, Wk
__device__ __half g_qh[(size_t)TOK * EE];
__device__ __half g_kh[(size_t)TOK * EE];
__device__ __half g_vt[(size_t)BB * HH * DD * SS];   // [b][h][d][s]
__device__ float  g_ctx[(size_t)TOK * EE];

// ---------------------------------------------------------------------------
// PTX helpers
// ---------------------------------------------------------------------------
__device__ __forceinline__ uint32_t smem_u32(const void* p) {
    uint32_t a;
    asm("{ .reg .u64 t; cvta.to.shared.u64 t, %1; cvt.u32.u64 %0, t; }"
        : "=r"(a) : "l"(p));
    return a;
}

#define CP_ASYNC16(sa, gp) \
    asm volatile("cp.async.cg.shared.global [%0], [%1], 16;" \
                 :: "r"(sa), "l"(gp))
#define CP_COMMIT() asm volatile("cp.async.commit_group;" ::: "memory")
#define CP_WAIT1()  asm volatile("cp.async.wait_group 1;" ::: "memory")
#define CP_WAIT0()  asm volatile("cp.async.wait_group 0;" ::: "memory")

#define LDSM4(R0, R1, R2, R3, ADDR) \
    asm volatile("ldmatrix.sync.aligned.m8n8.x4.shared.b16 {%0,%1,%2,%3}, [%4];" \
                 : "=r"(R0), "=r"(R1), "=r"(R2), "=r"(R3) : "r"(ADDR))
#define LDSM4T(R0, R1, R2, R3, ADDR) \
    asm volatile("ldmatrix.sync.aligned.m8n8.x4.trans.shared.b16 {%0,%1,%2,%3}, [%4];" \
                 : "=r"(R0), "=r"(R1), "=r"(R2), "=r"(R3) : "r"(ADDR))

// fp32-accumulate mma (GEMM, PV, l)
#define MMA16816(D, A0, A1, A2, A3, B0, B1) \
    asm volatile("mma.sync.aligned.m16n8k16.row.col.f32.f16.f16.f32 " \
                 "{%0,%1,%2,%3}, {%4,%5,%6,%7}, {%8,%9}, {%0,%1,%2,%3};" \
                 : "+f"((D)[0]), "+f"((D)[1]), "+f"((D)[2]), "+f"((D)[3]) \
                 : "r"(A0), "r"(A1), "r"(A2), "r"(A3), "r"(B0), "r"(B1))

// fp16-accumulate mma (attention S): D regs come out in PV A-fragment layout
#define MMA16816_H(D0, D1, A0, A1, A2, A3, B0, B1) \
    asm volatile("mma.sync.aligned.m16n8k16.row.col.f16.f16.f16.f16 " \
                 "{%0,%1}, {%2,%3,%4,%5}, {%6,%7}, {%0,%1};" \
                 : "+r"(D0), "+r"(D1) \
                 : "r"(A0), "r"(A1), "r"(A2), "r"(A3), "r"(B0), "r"(B1))

// exp2 on packed fp16x2, in place
#define EX2H2(R) asm("ex2.approx.f16x2 %0, %0;" : "+r"(R))

#define ONES_H2 0x3C003C00u   // (1.0h, 1.0h)

__device__ __forceinline__ uint32_t pack_h2(float a, float b) {
    __half2 h = __floats2half2_rn(a, b);
    return *reinterpret_cast<uint32_t*>(&h);
}

// ---------------------------------------------------------------------------
// Kernel 0a: X -> g_vt [b][h][d][s] fp16 AND g_xh row-major fp16.
// ---------------------------------------------------------------------------
__global__ __launch_bounds__(256) void vt_kernel(const float* __restrict__ X)
{
    __shared__ float sm[64][65];
    const int tid = threadIdx.x;
    const int bh = blockIdx.y, b = bh >> 4, h = bh & 15;
    const int s0 = blockIdx.x * 64;

#pragma unroll
    for (int r = 0; r < 4; ++r) {
        int idx = tid + r * 256;
        int row = idx >> 4;
        int c4  = (idx & 15) << 2;
        const size_t goff = ((size_t)(b * SS + s0 + row)) * EE + h * DD + c4;
        float4 v = *(const float4*)(X + goff);
        sm[row][c4 + 0] = v.x; sm[row][c4 + 1] = v.y;
        sm[row][c4 + 2] = v.z; sm[row][c4 + 3] = v.w;
        uint2 hx = make_uint2(pack_h2(v.x, v.y), pack_h2(v.z, v.w));
        *reinterpret_cast<uint2*>(g_xh + goff) = hx;
    }
    __syncthreads();
#pragma unroll
    for (int r = 0; r < 8; ++r) {
        int idx = tid + r * 256;
        int d  = idx >> 5;
        int s2 = (idx & 31) * 2;
        __half2 h2 = __floats2half2_rn(sm[s2][d], sm[s2 + 1][d]);
        *reinterpret_cast<__half2*>(g_vt + ((size_t)bh * DD + d) * SS + s0 + s2) = h2;
    }
}

// ---------------------------------------------------------------------------
// Kernel 0b: Wq/Wk -> fp16.
// ---------------------------------------------------------------------------
__global__ __launch_bounds__(256) void wconv_kernel(
    const float* __restrict__ Wq, const float* __restrict__ Wk)
{
    const float* src = (blockIdx.y == 0) ? Wq : Wk;
    __half* dst = g_wh[blockIdx.y];
    const size_t i4 = (size_t)blockIdx.x * 256 + threadIdx.x;
    float4 v = *(const float4*)(src + i4 * 4);
    uint2 hx = make_uint2(pack_h2(v.x, v.y), pack_h2(v.z, v.w));
    *reinterpret_cast<uint2*>(dst + i4 * 4) = hx;
}

// ---------------------------------------------------------------------------
// Kernel 1: split Q/K projection GEMM, fp16 mma, THREE-stage cp.async ring
// with ONE __syncthreads per chunk. grid (8, 64, 2), 256 thr = 8 warps.
// smem: A[3] 128x80B @0; B[3] 32x272B @30720. Total 56832 B.
// ---------------------------------------------------------------------------
#define GA_PITCH 80
#define GB_PITCH 272
#define G_SA(s) ((s) * 10240)
#define G_SB(s) (30720 + (s) * 8704)
#define G_SMEM_BYTES (30720 + 3 * 8704)   // 56832

__global__ __launch_bounds__(256) void gemm_qk_h()
{
    extern __shared__ char smg[];
    const uint32_t sb = smem_u32(smg);

    const __half* Xh = g_xh;
    const __half* Wh = g_wh[blockIdx.z];
    __half* C        = (blockIdx.z == 0) ? g_qh : g_kh;
    const float qsc  = (blockIdx.z == 0) ? QSCALE : 1.0f;

    const int m0 = blockIdx.y * 128;
    const int n0 = blockIdx.x * 128;
    const int tid = threadIdx.x;
    const int wid = tid >> 5;
    const int lane = tid & 31;
    const int gid = lane >> 2;
    const int tig = lane & 3;
    const int wm = (wid >> 1) * 32;
    const int wn = (wid & 1) * 64;

    float acc[2][8][4];
#pragma unroll
    for (int mt = 0; mt < 2; ++mt)
#pragma unroll
        for (int nt = 0; nt < 8; ++nt)
#pragma unroll
            for (int r = 0; r < 4; ++r) acc[mt][nt][r] = 0.f;

    // Per-thread load mapping (2 A f4 + 2 B f4 per chunk)
    const int arow0 = tid >> 2,          aseg0 = tid & 3;
    const int arow1 = (tid + 256) >> 2,  aseg1 = (tid + 256) & 3;
    const int brow0 = tid >> 4,          bseg0 = tid & 15;
    const int brow1 = (tid + 256) >> 4,  bseg1 = (tid + 256) & 15;

    // Prefetch chunks 0 and 1 into stages 0 and 1.
#pragma unroll
    for (int s = 0; s < 2; ++s) {
        const int k0 = s * 32;
        CP_ASYNC16(sb + G_SA(s) + arow0 * GA_PITCH + aseg0 * 16,
                   Xh + (size_t)(m0 + arow0) * EE + k0 + aseg0 * 8);
        CP_ASYNC16(sb + G_SA(s) + arow1 * GA_PITCH + aseg1 * 16,
                   Xh + (size_t)(m0 + arow1) * EE + k0 + aseg1 * 8);
        CP_ASYNC16(sb + G_SB(s) + brow0 * GB_PITCH + bseg0 * 16,
                   Wh + (size_t)(k0 + brow0) * EE + n0 + bseg0 * 8);
        CP_ASYNC16(sb + G_SB(s) + brow1 * GB_PITCH + bseg1 * 16,
                   Wh + (size_t)(k0 + brow1) * EE + n0 + bseg1 * 8);
        CP_COMMIT();
    }

    const uint32_t a_lm = (uint32_t)((lane & 15) * GA_PITCH + ((lane & 16) ? 16 : 0));
    const uint32_t b_lm = (uint32_t)((lane & 15) * GB_PITCH + ((lane & 16) ? 16 : 0));

    for (int ch = 0; ch < 32; ++ch) {
        if (ch < 31) { CP_WAIT1(); } else { CP_WAIT0(); }
        __syncthreads();   // single barrier per chunk

        // Prefetch chunk ch+2 into stage (ch+2)%3 (read last at iter ch-1;
        // the sync above guarantees those reads have completed).
        if (ch + 2 < 32) {
            const int k0 = (ch + 2) * 32;
            const int st = (ch + 2) % 3;
            CP_ASYNC16(sb + G_SA(st) + arow0 * GA_PITCH + aseg0 * 16,
                       Xh + (size_t)(m0 + arow0) * EE + k0 + aseg0 * 8);
            CP_ASYNC16(sb + G_SA(st) + arow1 * GA_PITCH + aseg1 * 16,
                       Xh + (size_t)(m0 + arow1) * EE + k0 + aseg1 * 8);
            CP_ASYNC16(sb + G_SB(st) + brow0 * GB_PITCH + bseg0 * 16,
                       Wh + (size_t)(k0 + brow0) * EE + n0 + bseg0 * 8);
            CP_ASYNC16(sb + G_SB(st) + brow1 * GB_PITCH + bseg1 * 16,
                       Wh + (size_t)(k0 + brow1) * EE + n0 + bseg1 * 8);
            CP_COMMIT();
        }

        const int cs = ch % 3;
        const uint32_t sa  = sb + G_SA(cs);
        const uint32_t sbf = sb + G_SB(cs);

#pragma unroll
        for (int ks = 0; ks < 2; ++ks) {
            uint32_t af[2][4];
#pragma unroll
            for (int mt = 0; mt < 2; ++mt) {
                LDSM4(af[mt][0], af[mt][1], af[mt][2], af[mt][3],
                      sa + (wm + mt * 16) * GA_PITCH + a_lm + ks * 32);
            }
#pragma unroll
            for (int np = 0; np < 4; ++np) {
                uint32_t b0, b1, b2, b3;
                LDSM4T(b0, b1, b2, b3,
                       sbf + ks * 16 * GB_PITCH + b_lm + (wn + np * 16) * 2);
                MMA16816(acc[0][2 * np + 0], af[0][0], af[0][1], af[0][2], af[0][3], b0, b1);
                MMA16816(acc[0][2 * np + 1], af[0][0], af[0][1], af[0][2], af[0][3], b2, b3);
                MMA16816(acc[1][2 * np + 0], af[1][0], af[1][1], af[1][2], af[1][3], b0, b1);
                MMA16816(acc[1][2 * np + 1], af[1][0], af[1][1], af[1][2], af[1][3], b2, b3);
            }
        }
    }

#pragma unroll
    for (int mt = 0; mt < 2; ++mt) {
        const int r0 = m0 + wm + mt * 16 + gid;
#pragma unroll
        for (int nt = 0; nt < 8; ++nt) {
            const int ncol = n0 + wn + nt * 8 + tig * 2;
            __half2 h0 = __floats2half2_rn(acc[mt][nt][0] * qsc, acc[mt][nt][1] * qsc);
            __half2 h1 = __floats2half2_rn(acc[mt][nt][2] * qsc, acc[mt][nt][3] * qsc);
            *reinterpret_cast<__half2*>(C + (size_t)(r0 + 0) * EE + ncol) = h0;
            *reinterpret_cast<__half2*>(C + (size_t)(r0 + 8) * EE + ncol) = h1;
        }
    }
}

// ---------------------------------------------------------------------------
// Kernel 2: flash attention (round-11 winner, verbatim). 128-query x 128-key
// tiles, fp16-D S-mma whose output registers ARE the PV A-fragments.
// smem: Q 128x144B @0; K[2] 128x144B @18432; V[2] 64x272B @55296.
// ---------------------------------------------------------------------------
#define AT_OQ    0
#define AT_OK    18432
#define AT_KBUF  18432
#define AT_OV    (18432 + 2 * 18432)        // 55296
#define AT_VBUF  17408
#define AT_SMEM_BYTES (AT_OV + 2 * AT_VBUF) // 90112

__global__ __launch_bounds__(256, 2) void attn_h()
{
    extern __shared__ char sma[];
    const uint32_t sb = smem_u32(sma);
    const int tid = threadIdx.x;
    const int wid = tid >> 5, lane = tid & 31;
    const int gid = lane >> 2, tig = lane & 3;
    const int wm = wid * 16;
    const int bh = blockIdx.y, b = bh >> 4, h = bh & 15;
    const int s0 = blockIdx.x * 128;

    const __half* qsrc = g_qh + ((size_t)(b * SS + s0)) * EE + h * DD;
    const __half* ksrc = g_kh + ((size_t)b * SS) * EE + h * DD;
    const __half* vsrc = g_vt + ((size_t)bh * DD) * SS;

    // Stage Q (128 rows x 64h) and tile 0 of K (128 keys) / V (64d x 128keys).
#pragma unroll
    for (int r = 0; r < 4; ++r) {
        int idx = tid + r * 256;
        int row = idx >> 3, seg = idx & 7;
        CP_ASYNC16(sb + AT_OQ + row * 144 + seg * 16,
                   qsrc + (size_t)row * EE + seg * 8);
    }
#pragma unroll
    for (int r = 0; r < 4; ++r) {
        int idx = tid + r * 256;
        int krow = idx >> 3, kseg = idx & 7;
        CP_ASYNC16(sb + AT_OK + krow * 144 + kseg * 16,
                   ksrc + (size_t)krow * EE + kseg * 8);
        int vrow = idx >> 4, vseg = idx & 15;
        CP_ASYNC16(sb + AT_OV + vrow * 272 + vseg * 16,
                   vsrc + (size_t)vrow * SS + vseg * 8);
    }
    CP_COMMIT();
    CP_WAIT0();
    __syncthreads();

    uint32_t qf[4][4];
    {
        const uint32_t qoff = sb + AT_OQ + (uint32_t)(wm + (lane & 15)) * 144
                              + ((lane & 16) ? 16u : 0u);
#pragma unroll
        for (int ks = 0; ks < 4; ++ks)
            LDSM4(qf[ks][0], qf[ks][1], qf[ks][2], qf[ks][3], qoff + 32 * ks);
    }

    float oacc[8][4];
#pragma unroll
    for (int nt = 0; nt < 8; ++nt)
#pragma unroll
        for (int r = 0; r < 4; ++r) oacc[nt][r] = 0.f;
    float lacc[4]  = {0.f, 0.f, 0.f, 0.f};
    float lacc2[4] = {0.f, 0.f, 0.f, 0.f};

    const uint32_t kmoff = (uint32_t)((lane & 7) * 144 + (lane >> 3) * 16);
    const uint32_t vmoff = (uint32_t)((lane & 7) * 272 + (lane >> 3) * 16);

    for (int kt = 0; kt < 16; ++kt) {
        const int buf = kt & 1;
        if (kt + 1 < 16) {
            const int t0n = (kt + 1) * 128;
            const int nb = buf ^ 1;
#pragma unroll
            for (int r = 0; r < 4; ++r) {
                int idx = tid + r * 256;
                int krow = idx >> 3, kseg = idx & 7;
                CP_ASYNC16(sb + AT_OK + nb * AT_KBUF + krow * 144 + kseg * 16,
                           ksrc + (size_t)(t0n + krow) * EE + kseg * 8);
                int vrow = idx >> 4, vseg = idx & 15;
                CP_ASYNC16(sb + AT_OV + nb * AT_VBUF + vrow * 272 + vseg * 16,
                           vsrc + (size_t)vrow * SS + t0n + vseg * 8);
            }
            CP_COMMIT();
            CP_WAIT1();
        } else {
            CP_WAIT0();
        }
        __syncthreads();

        const uint32_t kb = sb + AT_OK + buf * AT_KBUF + kmoff;
        const uint32_t vb = sb + AT_OV + buf * AT_VBUF + vmoff;

        // ---- per 32-key chunk: S (fp16 D) -> exp2 in place -> l -> PV ----
#pragma unroll
        for (int c = 0; c < 4; ++c) {
            uint32_t sh[4][2];
#pragma unroll
            for (int nt = 0; nt < 4; ++nt) { sh[nt][0] = 0u; sh[nt][1] = 0u; }

#pragma unroll
            for (int nt = 0; nt < 4; ++nt) {
                const int ntg = c * 4 + nt;
                uint32_t k0, k1, k2, k3, k4, k5, k6, k7;
                LDSM4(k0, k1, k2, k3, kb + ntg * 1152);
                LDSM4(k4, k5, k6, k7, kb + ntg * 1152 + 64);
                MMA16816_H(sh[nt][0], sh[nt][1], qf[0][0], qf[0][1], qf[0][2], qf[0][3], k0, k1);
                MMA16816_H(sh[nt][0], sh[nt][1], qf[1][0], qf[1][1], qf[1][2], qf[1][3], k2, k3);
                MMA16816_H(sh[nt][0], sh[nt][1], qf[2][0], qf[2][1], qf[2][2], qf[2][3], k4, k5);
                MMA16816_H(sh[nt][0], sh[nt][1], qf[3][0], qf[3][1], qf[3][2], qf[3][3], k6, k7);
            }

#pragma unroll
            for (int nt = 0; nt < 4; ++nt) { EX2H2(sh[nt][0]); EX2H2(sh[nt][1]); }

            MMA16816(lacc,  sh[0][0], sh[0][1], sh[1][0], sh[1][1], ONES_H2, ONES_H2);
            MMA16816(lacc2, sh[2][0], sh[2][1], sh[3][0], sh[3][1], ONES_H2, ONES_H2);

#pragma unroll
            for (int nt = 0; nt < 8; ++nt) {
                uint32_t v0, v1, v2, v3;
                LDSM4(v0, v1, v2, v3, vb + nt * 2176 + c * 64);
                MMA16816(oacc[nt], sh[0][0], sh[0][1], sh[1][0], sh[1][1], v0, v1);
                MMA16816(oacc[nt], sh[2][0], sh[2][1], sh[3][0], sh[3][1], v2, v3);
            }
        }
        __syncthreads();
    }

    const float li0 = 1.0f / (lacc[0] + lacc2[0]);
    const float li1 = 1.0f / (lacc[2] + lacc2[2]);

    float* op = g_ctx + ((size_t)(b * SS + s0 + wm + gid)) * EE + h * DD;
#pragma unroll
    for (int nt = 0; nt < 8; ++nt) {
        const int dcol = nt * 8 + tig * 2;
        float2 v0 = make_float2(oacc[nt][0] * li0, oacc[nt][1] * li0);
        float2 v1 = make_float2(oacc[nt][2] * li1, oacc[nt][3] * li1);
        *(float2*)(op + dcol) = v0;
        *(float2*)(op + (size_t)8 * EE + dcol) = v1;
    }
}

// ---------------------------------------------------------------------------
// Kernel 3: residual + LayerNorm (unchanged).
// ---------------------------------------------------------------------------
__global__ __launch_bounds__(256) void ln_kernel(
    const float* __restrict__ X,
    const float* __restrict__ w,
    const float* __restrict__ bias,
    float* __restrict__ out)
{
    const int token = blockIdx.x;
    const int tid = threadIdx.x;
    const float* cp = g_ctx + (size_t)token * EE;
    const float* xp = X + (size_t)token * EE;

    float4 c  = *(const float4*)(cp + tid * 4);
    float4 xv = *(const float4*)(xp + tid * 4);
    float y0 = c.x + xv.x, y1 = c.y + xv.y, y2 = c.z + xv.z, y3 = c.w + xv.w;

    float sum = y0 + y1 + y2 + y3;
    float sq  = y0 * y0 + y1 * y1 + y2 * y2 + y3 * y3;
#pragma unroll
    for (int off = 16; off > 0; off >>= 1) {
        sum += __shfl_xor_sync(0xffffffffu, sum, off);
        sq  += __shfl_xor_sync(0xffffffffu, sq,  off);
    }
    __shared__ float ws[8], wq[8];
    __shared__ float s_mu, s_rinv;
    const int lane = tid & 31, wrp = tid >> 5;
    if (lane == 0) { ws[wrp] = sum; wq[wrp] = sq; }
    __syncthreads();
    if (tid < 32) {
        float a  = (tid < 8) ? ws[tid] : 0.f;
        float b2 = (tid < 8) ? wq[tid] : 0.f;
#pragma unroll
        for (int off = 4; off > 0; off >>= 1) {
            a  += __shfl_xor_sync(0xffffffffu, a, off);
            b2 += __shfl_xor_sync(0xffffffffu, b2, off);
        }
        if (tid == 0) {
            float mu  = a * (1.0f / EE);
            float var = b2 * (1.0f / EE) - mu * mu;
            s_mu = mu;
            s_rinv = rsqrtf(var + LN_EPS);
        }
    }
    __syncthreads();
    const float mu = s_mu, rinv = s_rinv;
    float4 w4 = *(const float4*)(w + tid * 4);
    float4 b4 = *(const float4*)(bias + tid * 4);
    float4 o;
    o.x = (y0 - mu) * rinv * w4.x + b4.x;
    o.y = (y1 - mu) * rinv * w4.y + b4.y;
    o.z = (y2 - mu) * rinv * w4.z + b4.z;
    o.w = (y3 - mu) * rinv * w4.w + b4.w;
    *(float4*)(out + (size_t)token * EE + tid * 4) = o;
}

// ---------------------------------------------------------------------------
extern "C" void kernel_launch(void* const* d_in, const int* in_sizes, int n_in,
                              void* d_out, int out_size)
{
    const float* Wq = (const float*)d_in[0];
    const float* Wk = (const float*)d_in[1];
    const float* X  = (const float*)d_in[2];
    const float* lw = (const float*)d_in[3];
    const float* lb = (const float*)d_in[4];
    float* out = (float*)d_out;

    cudaFuncSetAttribute(gemm_qk_h,
                         cudaFuncAttributeMaxDynamicSharedMemorySize,
                         G_SMEM_BYTES);
    cudaFuncSetAttribute(attn_h,
                         cudaFuncAttributeMaxDynamicSharedMemorySize,
                         AT_SMEM_BYTES);

    wconv_kernel<<<dim3(1024, 2), 256>>>(Wq, Wk);
    vt_kernel<<<dim3(32, 64), 256>>>(X);
    gemm_qk_h<<<dim3(8, 64, 2), 256, G_SMEM_BYTES>>>();
    attn_h<<<dim3(16, 64), 256, AT_SMEM_BYTES>>>();
    ln_kernel<<<dim3(TOK), 256>>>(X, lw, lb, out);
}

// round 15
// speedup vs baseline: 1.1002x; 1.0466x over previous
#include <cuda_runtime.h>
#include <cuda_fp16.h>
#include <cstdint>
#include <math.h>

#define BB 4
#define SS 2048
#define EE 1024
#define HH 16
#define DD 64
#define TOK (BB * SS)
#define LN_EPS 1e-5f
// SCALE * log2(e): softmax done in exp2 domain
#define QSCALE 0.1803368801111244f

__device__ __half g_xh[(size_t)TOK * EE];            // fp16 copy of X
__device__ __half g_wh[2][(size_t)EE * EE];          // fp16 Wq, Wk
__device__ __half g_qh[(size_t)TOK * EE];
__device__ __half g_kh[(size_t)TOK * EE];
__device__ __half g_vt[(size_t)BB * HH * DD * SS];   // [b][h][d][s]
__device__ float  g_ctx[(size_t)TOK * EE];

// ---------------------------------------------------------------------------
// PTX helpers
// ---------------------------------------------------------------------------
__device__ __forceinline__ uint32_t smem_u32(const void* p) {
    uint32_t a;
    asm("{ .reg .u64 t; cvta.to.shared.u64 t, %1; cvt.u32.u64 %0, t; }"
        : "=r"(a) : "l"(p));
    return a;
}

#define CP_ASYNC16(sa, gp) \
    asm volatile("cp.async.cg.shared.global [%0], [%1], 16;" \
                 :: "r"(sa), "l"(gp))
#define CP_COMMIT() asm volatile("cp.async.commit_group;" ::: "memory")
#define CP_WAIT1()  asm volatile("cp.async.wait_group 1;" ::: "memory")
#define CP_WAIT0()  asm volatile("cp.async.wait_group 0;" ::: "memory")

#define LDSM4(R0, R1, R2, R3, ADDR) \
    asm volatile("ldmatrix.sync.aligned.m8n8.x4.shared.b16 {%0,%1,%2,%3}, [%4];" \
                 : "=r"(R0), "=r"(R1), "=r"(R2), "=r"(R3) : "r"(ADDR))
#define LDSM4T(R0, R1, R2, R3, ADDR) \
    asm volatile("ldmatrix.sync.aligned.m8n8.x4.trans.shared.b16 {%0,%1,%2,%3}, [%4];" \
                 : "=r"(R0), "=r"(R1), "=r"(R2), "=r"(R3) : "r"(ADDR))

// fp32-accumulate mma (GEMM, PV, l)
#define MMA16816(D, A0, A1, A2, A3, B0, B1) \
    asm volatile("mma.sync.aligned.m16n8k16.row.col.f32.f16.f16.f32 " \
                 "{%0,%1,%2,%3}, {%4,%5,%6,%7}, {%8,%9}, {%0,%1,%2,%3};" \
                 : "+f"((D)[0]), "+f"((D)[1]), "+f"((D)[2]), "+f"((D)[3]) \
                 : "r"(A0), "r"(A1), "r"(A2), "r"(A3), "r"(B0), "r"(B1))

// fp16-accumulate mma (attention S): D regs come out in PV A-fragment layout
#define MMA16816_H(D0, D1, A0, A1, A2, A3, B0, B1) \
    asm volatile("mma.sync.aligned.m16n8k16.row.col.f16.f16.f16.f16 " \
                 "{%0,%1}, {%2,%3,%4,%5}, {%6,%7}, {%0,%1};" \
                 : "+r"(D0), "+r"(D1) \
                 : "r"(A0), "r"(A1), "r"(A2), "r"(A3), "r"(B0), "r"(B1))

// exp2 on packed fp16x2, in place
#define EX2H2(R) asm("ex2.approx.f16x2 %0, %0;" : "+r"(R))

#define ONES_H2 0x3C003C00u   // (1.0h, 1.0h)

__device__ __forceinline__ uint32_t pack_h2(float a, float b) {
    __half2 h = __floats2half2_rn(a, b);
    return *reinterpret_cast<uint32_t*>(&h);
}

// ---------------------------------------------------------------------------
// Kernel 0a: X -> g_vt [b][h][d][s] fp16 AND g_xh row-major fp16.
// ---------------------------------------------------------------------------
__global__ __launch_bounds__(256) void vt_kernel(const float* __restrict__ X)
{
    __shared__ float sm[64][65];
    const int tid = threadIdx.x;
    const int bh = blockIdx.y, b = bh >> 4, h = bh & 15;
    const int s0 = blockIdx.x * 64;

#pragma unroll
    for (int r = 0; r < 4; ++r) {
        int idx = tid + r * 256;
        int row = idx >> 4;
        int c4  = (idx & 15) << 2;
        const size_t goff = ((size_t)(b * SS + s0 + row)) * EE + h * DD + c4;
        float4 v = *(const float4*)(X + goff);
        sm[row][c4 + 0] = v.x; sm[row][c4 + 1] = v.y;
        sm[row][c4 + 2] = v.z; sm[row][c4 + 3] = v.w;
        uint2 hx = make_uint2(pack_h2(v.x, v.y), pack_h2(v.z, v.w));
        *reinterpret_cast<uint2*>(g_xh + goff) = hx;
    }
    __syncthreads();
#pragma unroll
    for (int r = 0; r < 8; ++r) {
        int idx = tid + r * 256;
        int d  = idx >> 5;
        int s2 = (idx & 31) * 2;
        __half2 h2 = __floats2half2_rn(sm[s2][d], sm[s2 + 1][d]);
        *reinterpret_cast<__half2*>(g_vt + ((size_t)bh * DD + d) * SS + s0 + s2) = h2;
    }
}

// ---------------------------------------------------------------------------
// Kernel 0b: Wq/Wk -> fp16.
// ---------------------------------------------------------------------------
__global__ __launch_bounds__(256) void wconv_kernel(
    const float* __restrict__ Wq, const float* __restrict__ Wk)
{
    const float* src = (blockIdx.y == 0) ? Wq : Wk;
    __half* dst = g_wh[blockIdx.y];
    const size_t i4 = (size_t)blockIdx.x * 256 + threadIdx.x;
    float4 v = *(const float4*)(src + i4 * 4);
    uint2 hx = make_uint2(pack_h2(v.x, v.y), pack_h2(v.z, v.w));
    *reinterpret_cast<uint2*>(dst + i4 * 4) = hx;
}

// ---------------------------------------------------------------------------
// Kernel 1: split Q/K projection GEMM, fp16 mma, BK=64 chunks, 2-stage
// cp.async double buffer (round-11 structure, half the barriers).
// grid (8, 64, 2), 256 thr = 8 warps (4m x 2n), warp tile 32x64.
// smem: A[2] 128x144B; B[2] 64x272B. Total 71680 B (2 CTAs/SM fit).
// ---------------------------------------------------------------------------
#define GA_PITCH 144
#define GB_PITCH 272
#define G_SA(buf) ((buf) * 18432)
#define G_SB(buf) (36864 + (buf) * 17408)
#define G_SMEM_BYTES (36864 + 2 * 17408)   // 71680

__global__ __launch_bounds__(256) void gemm_qk_h()
{
    extern __shared__ char smg[];
    const uint32_t sb = smem_u32(smg);

    const __half* Xh = g_xh;
    const __half* Wh = g_wh[blockIdx.z];
    __half* C        = (blockIdx.z == 0) ? g_qh : g_kh;
    const float qsc  = (blockIdx.z == 0) ? QSCALE : 1.0f;

    const int m0 = blockIdx.y * 128;
    const int n0 = blockIdx.x * 128;
    const int tid = threadIdx.x;
    const int wid = tid >> 5;
    const int lane = tid & 31;
    const int gid = lane >> 2;
    const int tig = lane & 3;
    const int wm = (wid >> 1) * 32;
    const int wn = (wid & 1) * 64;

    float acc[2][8][4];
#pragma unroll
    for (int mt = 0; mt < 2; ++mt)
#pragma unroll
        for (int nt = 0; nt < 8; ++nt)
#pragma unroll
            for (int r = 0; r < 4; ++r) acc[mt][nt][r] = 0.f;

    // Prefetch chunk 0 into buf 0: A 128x64h (1024x16B), B 64x128h (1024x16B).
#pragma unroll
    for (int i = 0; i < 4; ++i) {
        int idx = tid + i * 256;
        int arow = idx >> 3, aseg = idx & 7;
        CP_ASYNC16(sb + G_SA(0) + arow * GA_PITCH + aseg * 16,
                   Xh + (size_t)(m0 + arow) * EE + aseg * 8);
        int brow = idx >> 4, bseg = idx & 15;
        CP_ASYNC16(sb + G_SB(0) + brow * GB_PITCH + bseg * 16,
                   Wh + (size_t)brow * EE + n0 + bseg * 8);
    }
    CP_COMMIT();

    const uint32_t a_lm = (uint32_t)((lane & 15) * GA_PITCH + ((lane & 16) ? 16 : 0));
    const uint32_t b_lm = (uint32_t)((lane & 15) * GB_PITCH + ((lane & 16) ? 16 : 0));

    for (int ch = 0; ch < 16; ++ch) {
        const int buf = ch & 1;
        if (ch + 1 < 16) {
            const int k0 = (ch + 1) * 64;
            const int nb = buf ^ 1;
#pragma unroll
            for (int i = 0; i < 4; ++i) {
                int idx = tid + i * 256;
                int arow = idx >> 3, aseg = idx & 7;
                CP_ASYNC16(sb + G_SA(nb) + arow * GA_PITCH + aseg * 16,
                           Xh + (size_t)(m0 + arow) * EE + k0 + aseg * 8);
                int brow = idx >> 4, bseg = idx & 15;
                CP_ASYNC16(sb + G_SB(nb) + brow * GB_PITCH + bseg * 16,
                           Wh + (size_t)(k0 + brow) * EE + n0 + bseg * 8);
            }
            CP_COMMIT();
            CP_WAIT1();
        } else {
            CP_WAIT0();
        }
        __syncthreads();

        const uint32_t sa  = sb + G_SA(buf);
        const uint32_t sbf = sb + G_SB(buf);

#pragma unroll
        for (int ks = 0; ks < 4; ++ks) {
            uint32_t af[2][4];
#pragma unroll
            for (int mt = 0; mt < 2; ++mt) {
                LDSM4(af[mt][0], af[mt][1], af[mt][2], af[mt][3],
                      sa + (wm + mt * 16) * GA_PITCH + a_lm + ks * 32);
            }
#pragma unroll
            for (int np = 0; np < 4; ++np) {
                uint32_t b0, b1, b2, b3;
                LDSM4T(b0, b1, b2, b3,
                       sbf + ks * 16 * GB_PITCH + b_lm + (wn + np * 16) * 2);
                MMA16816(acc[0][2 * np + 0], af[0][0], af[0][1], af[0][2], af[0][3], b0, b1);
                MMA16816(acc[0][2 * np + 1], af[0][0], af[0][1], af[0][2], af[0][3], b2, b3);
                MMA16816(acc[1][2 * np + 0], af[1][0], af[1][1], af[1][2], af[1][3], b0, b1);
                MMA16816(acc[1][2 * np + 1], af[1][0], af[1][1], af[1][2], af[1][3], b2, b3);
            }
        }
        __syncthreads();
    }

#pragma unroll
    for (int mt = 0; mt < 2; ++mt) {
        const int r0 = m0 + wm + mt * 16 + gid;
#pragma unroll
        for (int nt = 0; nt < 8; ++nt) {
            const int ncol = n0 + wn + nt * 8 + tig * 2;
            __half2 h0 = __floats2half2_rn(acc[mt][nt][0] * qsc, acc[mt][nt][1] * qsc);
            __half2 h1 = __floats2half2_rn(acc[mt][nt][2] * qsc, acc[mt][nt][3] * qsc);
            *reinterpret_cast<__half2*>(C + (size_t)(r0 + 0) * EE + ncol) = h0;
            *reinterpret_cast<__half2*>(C + (size_t)(r0 + 8) * EE + ncol) = h1;
        }
    }
}

// ---------------------------------------------------------------------------
// Kernel 2: flash attention (round-11 winner, verbatim). 128-query x 128-key
// tiles, fp16-D S-mma whose output registers ARE the PV A-fragments.
// smem: Q 128x144B @0; K[2] 128x144B @18432; V[2] 64x272B @55296.
// ---------------------------------------------------------------------------
#define AT_OQ    0
#define AT_OK    18432
#define AT_KBUF  18432
#define AT_OV    (18432 + 2 * 18432)        // 55296
#define AT_VBUF  17408
#define AT_SMEM_BYTES (AT_OV + 2 * AT_VBUF) // 90112

__global__ __launch_bounds__(256, 2) void attn_h()
{
    extern __shared__ char sma[];
    const uint32_t sb = smem_u32(sma);
    const int tid = threadIdx.x;
    const int wid = tid >> 5, lane = tid & 31;
    const int gid = lane >> 2, tig = lane & 3;
    const int wm = wid * 16;
    const int bh = blockIdx.y, b = bh >> 4, h = bh & 15;
    const int s0 = blockIdx.x * 128;

    const __half* qsrc = g_qh + ((size_t)(b * SS + s0)) * EE + h * DD;
    const __half* ksrc = g_kh + ((size_t)b * SS) * EE + h * DD;
    const __half* vsrc = g_vt + ((size_t)bh * DD) * SS;

    // Stage Q (128 rows x 64h) and tile 0 of K (128 keys) / V (64d x 128keys).
#pragma unroll
    for (int r = 0; r < 4; ++r) {
        int idx = tid + r * 256;
        int row = idx >> 3, seg = idx & 7;
        CP_ASYNC16(sb + AT_OQ + row * 144 + seg * 16,
                   qsrc + (size_t)row * EE + seg * 8);
    }
#pragma unroll
    for (int r = 0; r < 4; ++r) {
        int idx = tid + r * 256;
        int krow = idx >> 3, kseg = idx & 7;
        CP_ASYNC16(sb + AT_OK + krow * 144 + kseg * 16,
                   ksrc + (size_t)krow * EE + kseg * 8);
        int vrow = idx >> 4, vseg = idx & 15;
        CP_ASYNC16(sb + AT_OV + vrow * 272 + vseg * 16,
                   vsrc + (size_t)vrow * SS + vseg * 8);
    }
    CP_COMMIT();
    CP_WAIT0();
    __syncthreads();

    uint32_t qf[4][4];
    {
        const uint32_t qoff = sb + AT_OQ + (uint32_t)(wm + (lane & 15)) * 144
                              + ((lane & 16) ? 16u : 0u);
#pragma unroll
        for (int ks = 0; ks < 4; ++ks)
            LDSM4(qf[ks][0], qf[ks][1], qf[ks][2], qf[ks][3], qoff + 32 * ks);
    }

    float oacc[8][4];
#pragma unroll
    for (int nt = 0; nt < 8; ++nt)
#pragma unroll
        for (int r = 0; r < 4; ++r) oacc[nt][r] = 0.f;
    float lacc[4]  = {0.f, 0.f, 0.f, 0.f};
    float lacc2[4] = {0.f, 0.f, 0.f, 0.f};

    const uint32_t kmoff = (uint32_t)((lane & 7) * 144 + (lane >> 3) * 16);
    const uint32_t vmoff = (uint32_t)((lane & 7) * 272 + (lane >> 3) * 16);

    for (int kt = 0; kt < 16; ++kt) {
        const int buf = kt & 1;
        if (kt + 1 < 16) {
            const int t0n = (kt + 1) * 128;
            const int nb = buf ^ 1;
#pragma unroll
            for (int r = 0; r < 4; ++r) {
                int idx = tid + r * 256;
                int krow = idx >> 3, kseg = idx & 7;
                CP_ASYNC16(sb + AT_OK + nb * AT_KBUF + krow * 144 + kseg * 16,
                           ksrc + (size_t)(t0n + krow) * EE + kseg * 8);
                int vrow = idx >> 4, vseg = idx & 15;
                CP_ASYNC16(sb + AT_OV + nb * AT_VBUF + vrow * 272 + vseg * 16,
                           vsrc + (size_t)vrow * SS + t0n + vseg * 8);
            }
            CP_COMMIT();
            CP_WAIT1();
        } else {
            CP_WAIT0();
        }
        __syncthreads();

        const uint32_t kb = sb + AT_OK + buf * AT_KBUF + kmoff;
        const uint32_t vb = sb + AT_OV + buf * AT_VBUF + vmoff;

        // ---- per 32-key chunk: S (fp16 D) -> exp2 in place -> l -> PV ----
#pragma unroll
        for (int c = 0; c < 4; ++c) {
            uint32_t sh[4][2];
#pragma unroll
            for (int nt = 0; nt < 4; ++nt) { sh[nt][0] = 0u; sh[nt][1] = 0u; }

#pragma unroll
            for (int nt = 0; nt < 4; ++nt) {
                const int ntg = c * 4 + nt;
                uint32_t k0, k1, k2, k3, k4, k5, k6, k7;
                LDSM4(k0, k1, k2, k3, kb + ntg * 1152);
                LDSM4(k4, k5, k6, k7, kb + ntg * 1152 + 64);
                MMA16816_H(sh[nt][0], sh[nt][1], qf[0][0], qf[0][1], qf[0][2], qf[0][3], k0, k1);
                MMA16816_H(sh[nt][0], sh[nt][1], qf[1][0], qf[1][1], qf[1][2], qf[1][3], k2, k3);
                MMA16816_H(sh[nt][0], sh[nt][1], qf[2][0], qf[2][1], qf[2][2], qf[2][3], k4, k5);
                MMA16816_H(sh[nt][0], sh[nt][1], qf[3][0], qf[3][1], qf[3][2], qf[3][3], k6, k7);
            }

#pragma unroll
            for (int nt = 0; nt < 4; ++nt) { EX2H2(sh[nt][0]); EX2H2(sh[nt][1]); }

            MMA16816(lacc,  sh[0][0], sh[0][1], sh[1][0], sh[1][1], ONES_H2, ONES_H2);
            MMA16816(lacc2, sh[2][0], sh[2][1], sh[3][0], sh[3][1], ONES_H2, ONES_H2);

#pragma unroll
            for (int nt = 0; nt < 8; ++nt) {
                uint32_t v0, v1, v2, v3;
                LDSM4(v0, v1, v2, v3, vb + nt * 2176 + c * 64);
                MMA16816(oacc[nt], sh[0][0], sh[0][1], sh[1][0], sh[1][1], v0, v1);
                MMA16816(oacc[nt], sh[2][0], sh[2][1], sh[3][0], sh[3][1], v2, v3);
            }
        }
        __syncthreads();
    }

    const float li0 = 1.0f / (lacc[0] + lacc2[0]);
    const float li1 = 1.0f / (lacc[2] + lacc2[2]);

    float* op = g_ctx + ((size_t)(b * SS + s0 + wm + gid)) * EE + h * DD;
#pragma unroll
    for (int nt = 0; nt < 8; ++nt) {
        const int dcol = nt * 8 + tig * 2;
        float2 v0 = make_float2(oacc[nt][0] * li0, oacc[nt][1] * li0);
        float2 v1 = make_float2(oacc[nt][2] * li1, oacc[nt][3] * li1);
        *(float2*)(op + dcol) = v0;
        *(float2*)(op + (size_t)8 * EE + dcol) = v1;
    }
}

// ---------------------------------------------------------------------------
// Kernel 3: residual + LayerNorm (unchanged).
// ---------------------------------------------------------------------------
__global__ __launch_bounds__(256) void ln_kernel(
    const float* __restrict__ X,
    const float* __restrict__ w,
    const float* __restrict__ bias,
    float* __restrict__ out)
{
    const int token = blockIdx.x;
    const int tid = threadIdx.x;
    const float* cp = g_ctx + (size_t)token * EE;
    const float* xp = X + (size_t)token * EE;

    float4 c  = *(const float4*)(cp + tid * 4);
    float4 xv = *(const float4*)(xp + tid * 4);
    float y0 = c.x + xv.x, y1 = c.y + xv.y, y2 = c.z + xv.z, y3 = c.w + xv.w;

    float sum = y0 + y1 + y2 + y3;
    float sq  = y0 * y0 + y1 * y1 + y2 * y2 + y3 * y3;
#pragma unroll
    for (int off = 16; off > 0; off >>= 1) {
        sum += __shfl_xor_sync(0xffffffffu, sum, off);
        sq  += __shfl_xor_sync(0xffffffffu, sq,  off);
    }
    __shared__ float ws[8], wq[8];
    __shared__ float s_mu, s_rinv;
    const int lane = tid & 31, wrp = tid >> 5;
    if (lane == 0) { ws[wrp] = sum; wq[wrp] = sq; }
    __syncthreads();
    if (tid < 32) {
        float a  = (tid < 8) ? ws[tid] : 0.f;
        float b2 = (tid < 8) ? wq[tid] : 0.f;
#pragma unroll
        for (int off = 4; off > 0; off >>= 1) {
            a  += __shfl_xor_sync(0xffffffffu, a, off);
            b2 += __shfl_xor_sync(0xffffffffu, b2, off);
        }
        if (tid == 0) {
            float mu  = a * (1.0f / EE);
            float var = b2 * (1.0f / EE) - mu * mu;
            s_mu = mu;
            s_rinv = rsqrtf(var + LN_EPS);
        }
    }
    __syncthreads();
    const float mu = s_mu, rinv = s_rinv;
    float4 w4 = *(const float4*)(w + tid * 4);
    float4 b4 = *(const float4*)(bias + tid * 4);
    float4 o;
    o.x = (y0 - mu) * rinv * w4.x + b4.x;
    o.y = (y1 - mu) * rinv * w4.y + b4.y;
    o.z = (y2 - mu) * rinv * w4.z + b4.z;
    o.w = (y3 - mu) * rinv * w4.w + b4.w;
    *(float4*)(out + (size_t)token * EE + tid * 4) = o;
}

// ---------------------------------------------------------------------------
extern "C" void kernel_launch(void* const* d_in, const int* in_sizes, int n_in,
                              void* d_out, int out_size)
{
    const float* Wq = (const float*)d_in[0];
    const float* Wk = (const float*)d_in[1];
    const float* X  = (const float*)d_in[2];
    const float* lw = (const float*)d_in[3];
    const float* lb = (const float*)d_in[4];
    float* out = (float*)d_out;

    cudaFuncSetAttribute(gemm_qk_h,
                         cudaFuncAttributeMaxDynamicSharedMemorySize,
                         G_SMEM_BYTES);
    cudaFuncSetAttribute(attn_h,
                         cudaFuncAttributeMaxDynamicSharedMemorySize,
                         AT_SMEM_BYTES);

    wconv_kernel<<<dim3(1024, 2), 256>>>(Wq, Wk);
    vt_kernel<<<dim3(32, 64), 256>>>(X);
    gemm_qk_h<<<dim3(8, 64, 2), 256, G_SMEM_BYTES>>>();
    attn_h<<<dim3(16, 64), 256, AT_SMEM_BYTES>>>();
    ln_kernel<<<dim3(TOK), 256>>>(X, lw, lb, out);
}

// round 16
// speedup vs baseline: 1.1122x; 1.0108x over previous
#include <cuda_runtime.h>
#include <cuda_fp16.h>
#include <cstdint>
#include <math.h>

#define BB 4
#define SS 2048
#define EE 1024
#define HH 16
#define DD 64
#define TOK (BB * SS)
#define LN_EPS 1e-5f
// SCALE * log2(e): softmax done in exp2 domain
#define QSCALE 0.1803368801111244f

__device__ __half g_xh[(size_t)TOK * EE];            // fp16 copy of X
__device__ __half g_wh[2][(size_t)EE * EE];          // fp16 Wq, Wk
__device__ __half g_qh[(size_t)TOK * EE];
__device__ __half g_kh[(size_t)TOK * EE];
__device__ __half g_vt[(size_t)BB * HH * DD * SS];   // [b][h][d][s]
__device__ float  g_ctx[(size_t)TOK * EE];

// ---------------------------------------------------------------------------
// PTX helpers
// ---------------------------------------------------------------------------
__device__ __forceinline__ uint32_t smem_u32(const void* p) {
    uint32_t a;
    asm("{ .reg .u64 t; cvta.to.shared.u64 t, %1; cvt.u32.u64 %0, t; }"
        : "=r"(a) : "l"(p));
    return a;
}

#define CP_ASYNC16(sa, gp) \
    asm volatile("cp.async.cg.shared.global [%0], [%1], 16;" \
                 :: "r"(sa), "l"(gp))
#define CP_COMMIT() asm volatile("cp.async.commit_group;" ::: "memory")
#define CP_WAIT0()  asm volatile("cp.async.wait_group 0;" ::: "memory")

#define LDSM4(R0, R1, R2, R3, ADDR) \
    asm volatile("ldmatrix.sync.aligned.m8n8.x4.shared.b16 {%0,%1,%2,%3}, [%4];" \
                 : "=r"(R0), "=r"(R1), "=r"(R2), "=r"(R3) : "r"(ADDR))
#define LDSM4T(R0, R1, R2, R3, ADDR) \
    asm volatile("ldmatrix.sync.aligned.m8n8.x4.trans.shared.b16 {%0,%1,%2,%3}, [%4];" \
                 : "=r"(R0), "=r"(R1), "=r"(R2), "=r"(R3) : "r"(ADDR))

// fp32-accumulate mma (GEMM, PV, l)
#define MMA16816(D, A0, A1, A2, A3, B0, B1) \
    asm volatile("mma.sync.aligned.m16n8k16.row.col.f32.f16.f16.f32 " \
                 "{%0,%1,%2,%3}, {%4,%5,%6,%7}, {%8,%9}, {%0,%1,%2,%3};" \
                 : "+f"((D)[0]), "+f"((D)[1]), "+f"((D)[2]), "+f"((D)[3]) \
                 : "r"(A0), "r"(A1), "r"(A2), "r"(A3), "r"(B0), "r"(B1))

// fp16-accumulate mma (attention S): D regs come out in PV A-fragment layout
#define MMA16816_H(D0, D1, A0, A1, A2, A3, B0, B1) \
    asm volatile("mma.sync.aligned.m16n8k16.row.col.f16.f16.f16.f16 " \
                 "{%0,%1}, {%2,%3,%4,%5}, {%6,%7}, {%0,%1};" \
                 : "+r"(D0), "+r"(D1) \
                 : "r"(A0), "r"(A1), "r"(A2), "r"(A3), "r"(B0), "r"(B1))

// exp2 on packed fp16x2, in place
#define EX2H2(R) asm("ex2.approx.f16x2 %0, %0;" : "+r"(R))

#define ONES_H2 0x3C003C00u   // (1.0h, 1.0h)

__device__ __forceinline__ uint32_t pack_h2(float a, float b) {
    __half2 h = __floats2half2_rn(a, b);
    return *reinterpret_cast<uint32_t*>(&h);
}

// ---------------------------------------------------------------------------
// Kernel 0a: X -> g_vt [b][h][d][s] fp16 AND g_xh row-major fp16.
// ---------------------------------------------------------------------------
__global__ __launch_bounds__(256) void vt_kernel(const float* __restrict__ X)
{
    __shared__ float sm[64][65];
    const int tid = threadIdx.x;
    const int bh = blockIdx.y, b = bh >> 4, h = bh & 15;
    const int s0 = blockIdx.x * 64;

#pragma unroll
    for (int r = 0; r < 4; ++r) {
        int idx = tid + r * 256;
        int row = idx >> 4;
        int c4  = (idx & 15) << 2;
        const size_t goff = ((size_t)(b * SS + s0 + row)) * EE + h * DD + c4;
        float4 v = *(const float4*)(X + goff);
        sm[row][c4 + 0] = v.x; sm[row][c4 + 1] = v.y;
        sm[row][c4 + 2] = v.z; sm[row][c4 + 3] = v.w;
        uint2 hx = make_uint2(pack_h2(v.x, v.y), pack_h2(v.z, v.w));
        *reinterpret_cast<uint2*>(g_xh + goff) = hx;
    }
    __syncthreads();
#pragma unroll
    for (int r = 0; r < 8; ++r) {
        int idx = tid + r * 256;
        int d  = idx >> 5;
        int s2 = (idx & 31) * 2;
        __half2 h2 = __floats2half2_rn(sm[s2][d], sm[s2 + 1][d]);
        *reinterpret_cast<__half2*>(g_vt + ((size_t)bh * DD + d) * SS + s0 + s2) = h2;
    }
}

// ---------------------------------------------------------------------------
// Kernel 0b: Wq/Wk -> fp16.
// ---------------------------------------------------------------------------
__global__ __launch_bounds__(256) void wconv_kernel(
    const float* __restrict__ Wq, const float* __restrict__ Wk)
{
    const float* src = (blockIdx.y == 0) ? Wq : Wk;
    __half* dst = g_wh[blockIdx.y];
    const size_t i4 = (size_t)blockIdx.x * 256 + threadIdx.x;
    float4 v = *(const float4*)(src + i4 * 4);
    uint2 hx = make_uint2(pack_h2(v.x, v.y), pack_h2(v.z, v.w));
    *reinterpret_cast<uint2*>(dst + i4 * 4) = hx;
}

// ---------------------------------------------------------------------------
// Kernel 1: split Q/K projection GEMM, fp16 mma, BK=64 chunks, 2-stage
// cp.async double buffer with ONE barrier per chunk:
//   wait0 -> sync -> prefetch(ch+1) -> compute(ch)
// grid (8, 64, 2), 256 thr = 8 warps (4m x 2n), warp tile 32x64.
// smem: A[2] 128x144B; B[2] 64x272B. Total 71680 B (2 CTAs/SM fit).
// ---------------------------------------------------------------------------
#define GA_PITCH 144
#define GB_PITCH 272
#define G_SA(buf) ((buf) * 18432)
#define G_SB(buf) (36864 + (buf) * 17408)
#define G_SMEM_BYTES (36864 + 2 * 17408)   // 71680

__global__ __launch_bounds__(256) void gemm_qk_h()
{
    extern __shared__ char smg[];
    const uint32_t sb = smem_u32(smg);

    const __half* Xh = g_xh;
    const __half* Wh = g_wh[blockIdx.z];
    __half* C        = (blockIdx.z == 0) ? g_qh : g_kh;
    const float qsc  = (blockIdx.z == 0) ? QSCALE : 1.0f;

    const int m0 = blockIdx.y * 128;
    const int n0 = blockIdx.x * 128;
    const int tid = threadIdx.x;
    const int wid = tid >> 5;
    const int lane = tid & 31;
    const int gid = lane >> 2;
    const int tig = lane & 3;
    const int wm = (wid >> 1) * 32;
    const int wn = (wid & 1) * 64;

    float acc[2][8][4];
#pragma unroll
    for (int mt = 0; mt < 2; ++mt)
#pragma unroll
        for (int nt = 0; nt < 8; ++nt)
#pragma unroll
            for (int r = 0; r < 4; ++r) acc[mt][nt][r] = 0.f;

    // Prefetch chunk 0 into buf 0: A 128x64h (1024x16B), B 64x128h (1024x16B).
#pragma unroll
    for (int i = 0; i < 4; ++i) {
        int idx = tid + i * 256;
        int arow = idx >> 3, aseg = idx & 7;
        CP_ASYNC16(sb + G_SA(0) + arow * GA_PITCH + aseg * 16,
                   Xh + (size_t)(m0 + arow) * EE + aseg * 8);
        int brow = idx >> 4, bseg = idx & 15;
        CP_ASYNC16(sb + G_SB(0) + brow * GB_PITCH + bseg * 16,
                   Wh + (size_t)brow * EE + n0 + bseg * 8);
    }
    CP_COMMIT();

    const uint32_t a_lm = (uint32_t)((lane & 15) * GA_PITCH + ((lane & 16) ? 16 : 0));
    const uint32_t b_lm = (uint32_t)((lane & 15) * GB_PITCH + ((lane & 16) ? 16 : 0));

    for (int ch = 0; ch < 16; ++ch) {
        const int buf = ch & 1;
        // Wait for chunk ch's data (the only outstanding group), then one
        // barrier: makes data visible AND proves all warps finished reading
        // buffer buf^1 (last touched at iteration ch-1).
        CP_WAIT0();
        __syncthreads();

        // Prefetch chunk ch+1 into buf^1 (now free) — overlaps compute below.
        if (ch + 1 < 16) {
            const int k0 = (ch + 1) * 64;
            const int nb = buf ^ 1;
#pragma unroll
            for (int i = 0; i < 4; ++i) {
                int idx = tid + i * 256;
                int arow = idx >> 3, aseg = idx & 7;
                CP_ASYNC16(sb + G_SA(nb) + arow * GA_PITCH + aseg * 16,
                           Xh + (size_t)(m0 + arow) * EE + k0 + aseg * 8);
                int brow = idx >> 4, bseg = idx & 15;
                CP_ASYNC16(sb + G_SB(nb) + brow * GB_PITCH + bseg * 16,
                           Wh + (size_t)(k0 + brow) * EE + n0 + bseg * 8);
            }
            CP_COMMIT();
        }

        const uint32_t sa  = sb + G_SA(buf);
        const uint32_t sbf = sb + G_SB(buf);

#pragma unroll
        for (int ks = 0; ks < 4; ++ks) {
            uint32_t af[2][4];
#pragma unroll
            for (int mt = 0; mt < 2; ++mt) {
                LDSM4(af[mt][0], af[mt][1], af[mt][2], af[mt][3],
                      sa + (wm + mt * 16) * GA_PITCH + a_lm + ks * 32);
            }
#pragma unroll
            for (int np = 0; np < 4; ++np) {
                uint32_t b0, b1, b2, b3;
                LDSM4T(b0, b1, b2, b3,
                       sbf + ks * 16 * GB_PITCH + b_lm + (wn + np * 16) * 2);
                MMA16816(acc[0][2 * np + 0], af[0][0], af[0][1], af[0][2], af[0][3], b0, b1);
                MMA16816(acc[0][2 * np + 1], af[0][0], af[0][1], af[0][2], af[0][3], b2, b3);
                MMA16816(acc[1][2 * np + 0], af[1][0], af[1][1], af[1][2], af[1][3], b0, b1);
                MMA16816(acc[1][2 * np + 1], af[1][0], af[1][1], af[1][2], af[1][3], b2, b3);
            }
        }
    }

#pragma unroll
    for (int mt = 0; mt < 2; ++mt) {
        const int r0 = m0 + wm + mt * 16 + gid;
#pragma unroll
        for (int nt = 0; nt < 8; ++nt) {
            const int ncol = n0 + wn + nt * 8 + tig * 2;
            __half2 h0 = __floats2half2_rn(acc[mt][nt][0] * qsc, acc[mt][nt][1] * qsc);
            __half2 h1 = __floats2half2_rn(acc[mt][nt][2] * qsc, acc[mt][nt][3] * qsc);
            *reinterpret_cast<__half2*>(C + (size_t)(r0 + 0) * EE + ncol) = h0;
            *reinterpret_cast<__half2*>(C + (size_t)(r0 + 8) * EE + ncol) = h1;
        }
    }
}

// ---------------------------------------------------------------------------
// Kernel 2: flash attention (round-11 structure), ONE barrier per tile:
//   wait0 -> sync -> prefetch(kt+1) -> compute(kt)
// smem: Q 128x144B @0; K[2] 128x144B @18432; V[2] 64x272B @55296.
// ---------------------------------------------------------------------------
#define AT_OQ    0
#define AT_OK    18432
#define AT_KBUF  18432
#define AT_OV    (18432 + 2 * 18432)        // 55296
#define AT_VBUF  17408
#define AT_SMEM_BYTES (AT_OV + 2 * AT_VBUF) // 90112

__global__ __launch_bounds__(256, 2) void attn_h()
{
    extern __shared__ char sma[];
    const uint32_t sb = smem_u32(sma);
    const int tid = threadIdx.x;
    const int wid = tid >> 5, lane = tid & 31;
    const int gid = lane >> 2, tig = lane & 3;
    const int wm = wid * 16;
    const int bh = blockIdx.y, b = bh >> 4, h = bh & 15;
    const int s0 = blockIdx.x * 128;

    const __half* qsrc = g_qh + ((size_t)(b * SS + s0)) * EE + h * DD;
    const __half* ksrc = g_kh + ((size_t)b * SS) * EE + h * DD;
    const __half* vsrc = g_vt + ((size_t)bh * DD) * SS;

    // Stage Q (128 rows x 64h) and tile 0 of K (128 keys) / V (64d x 128keys).
#pragma unroll
    for (int r = 0; r < 4; ++r) {
        int idx = tid + r * 256;
        int row = idx >> 3, seg = idx & 7;
        CP_ASYNC16(sb + AT_OQ + row * 144 + seg * 16,
                   qsrc + (size_t)row * EE + seg * 8);
    }
#pragma unroll
    for (int r = 0; r < 4; ++r) {
        int idx = tid + r * 256;
        int krow = idx >> 3, kseg = idx & 7;
        CP_ASYNC16(sb + AT_OK + krow * 144 + kseg * 16,
                   ksrc + (size_t)krow * EE + kseg * 8);
        int vrow = idx >> 4, vseg = idx & 15;
        CP_ASYNC16(sb + AT_OV + vrow * 272 + vseg * 16,
                   vsrc + (size_t)vrow * SS + vseg * 8);
    }
    CP_COMMIT();
    CP_WAIT0();
    __syncthreads();

    uint32_t qf[4][4];
    {
        const uint32_t qoff = sb + AT_OQ + (uint32_t)(wm + (lane & 15)) * 144
                              + ((lane & 16) ? 16u : 0u);
#pragma unroll
        for (int ks = 0; ks < 4; ++ks)
            LDSM4(qf[ks][0], qf[ks][1], qf[ks][2], qf[ks][3], qoff + 32 * ks);
    }

    float oacc[8][4];
#pragma unroll
    for (int nt = 0; nt < 8; ++nt)
#pragma unroll
        for (int r = 0; r < 4; ++r) oacc[nt][r] = 0.f;
    float lacc[4]  = {0.f, 0.f, 0.f, 0.f};
    float lacc2[4] = {0.f, 0.f, 0.f, 0.f};

    const uint32_t kmoff = (uint32_t)((lane & 7) * 144 + (lane >> 3) * 16);
    const uint32_t vmoff = (uint32_t)((lane & 7) * 272 + (lane >> 3) * 16);

    for (int kt = 0; kt < 16; ++kt) {
        const int buf = kt & 1;
        // Invariant at loop top: tile kt's data visible (prologue or the
        // wait+sync at the end of the previous iteration's head).
        if (kt > 0) {
            CP_WAIT0();        // only group kt is outstanding
            __syncthreads();   // visibility + proves buf^1 reads finished
        }
        // Prefetch tile kt+1 into buf^1 (free: last read at kt-1, all warps
        // past the barrier above). Overlaps the compute below.
        if (kt + 1 < 16) {
            const int t0n = (kt + 1) * 128;
            const int nb = buf ^ 1;
#pragma unroll
            for (int r = 0; r < 4; ++r) {
                int idx = tid + r * 256;
                int krow = idx >> 3, kseg = idx & 7;
                CP_ASYNC16(sb + AT_OK + nb * AT_KBUF + krow * 144 + kseg * 16,
                           ksrc + (size_t)(t0n + krow) * EE + kseg * 8);
                int vrow = idx >> 4, vseg = idx & 15;
                CP_ASYNC16(sb + AT_OV + nb * AT_VBUF + vrow * 272 + vseg * 16,
                           vsrc + (size_t)vrow * SS + t0n + vseg * 8);
            }
            CP_COMMIT();
        }

        const uint32_t kb = sb + AT_OK + buf * AT_KBUF + kmoff;
        const uint32_t vb = sb + AT_OV + buf * AT_VBUF + vmoff;

        // ---- per 32-key chunk: S (fp16 D) -> exp2 in place -> l -> PV ----
#pragma unroll
        for (int c = 0; c < 4; ++c) {
            uint32_t sh[4][2];
#pragma unroll
            for (int nt = 0; nt < 4; ++nt) { sh[nt][0] = 0u; sh[nt][1] = 0u; }

#pragma unroll
            for (int nt = 0; nt < 4; ++nt) {
                const int ntg = c * 4 + nt;
                uint32_t k0, k1, k2, k3, k4, k5, k6, k7;
                LDSM4(k0, k1, k2, k3, kb + ntg * 1152);
                LDSM4(k4, k5, k6, k7, kb + ntg * 1152 + 64);
                MMA16816_H(sh[nt][0], sh[nt][1], qf[0][0], qf[0][1], qf[0][2], qf[0][3], k0, k1);
                MMA16816_H(sh[nt][0], sh[nt][1], qf[1][0], qf[1][1], qf[1][2], qf[1][3], k2, k3);
                MMA16816_H(sh[nt][0], sh[nt][1], qf[2][0], qf[2][1], qf[2][2], qf[2][3], k4, k5);
                MMA16816_H(sh[nt][0], sh[nt][1], qf[3][0], qf[3][1], qf[3][2], qf[3][3], k6, k7);
            }

#pragma unroll
            for (int nt = 0; nt < 4; ++nt) { EX2H2(sh[nt][0]); EX2H2(sh[nt][1]); }

            MMA16816(lacc,  sh[0][0], sh[0][1], sh[1][0], sh[1][1], ONES_H2, ONES_H2);
            MMA16816(lacc2, sh[2][0], sh[2][1], sh[3][0], sh[3][1], ONES_H2, ONES_H2);

#pragma unroll
            for (int nt = 0; nt < 8; ++nt) {
                uint32_t v0, v1, v2, v3;
                LDSM4(v0, v1, v2, v3, vb + nt * 2176 + c * 64);
                MMA16816(oacc[nt], sh[0][0], sh[0][1], sh[1][0], sh[1][1], v0, v1);
                MMA16816(oacc[nt], sh[2][0], sh[2][1], sh[3][0], sh[3][1], v2, v3);
            }
        }
    }

    const float li0 = 1.0f / (lacc[0] + lacc2[0]);
    const float li1 = 1.0f / (lacc[2] + lacc2[2]);

    float* op = g_ctx + ((size_t)(b * SS + s0 + wm + gid)) * EE + h * DD;
#pragma unroll
    for (int nt = 0; nt < 8; ++nt) {
        const int dcol = nt * 8 + tig * 2;
        float2 v0 = make_float2(oacc[nt][0] * li0, oacc[nt][1] * li0);
        float2 v1 = make_float2(oacc[nt][2] * li1, oacc[nt][3] * li1);
        *(float2*)(op + dcol) = v0;
        *(float2*)(op + (size_t)8 * EE + dcol) = v1;
    }
}

// ---------------------------------------------------------------------------
// Kernel 3: residual + LayerNorm (unchanged).
// ---------------------------------------------------------------------------
__global__ __launch_bounds__(256) void ln_kernel(
    const float* __restrict__ X,
    const float* __restrict__ w,
    const float* __restrict__ bias,
    float* __restrict__ out)
{
    const int token = blockIdx.x;
    const int tid = threadIdx.x;
    const float* cp = g_ctx + (size_t)token * EE;
    const float* xp = X + (size_t)token * EE;

    float4 c  = *(const float4*)(cp + tid * 4);
    float4 xv = *(const float4*)(xp + tid * 4);
    float y0 = c.x + xv.x, y1 = c.y + xv.y, y2 = c.z + xv.z, y3 = c.w + xv.w;

    float sum = y0 + y1 + y2 + y3;
    float sq  = y0 * y0 + y1 * y1 + y2 * y2 + y3 * y3;
#pragma unroll
    for (int off = 16; off > 0; off >>= 1) {
        sum += __shfl_xor_sync(0xffffffffu, sum, off);
        sq  += __shfl_xor_sync(0xffffffffu, sq,  off);
    }
    __shared__ float ws[8], wq[8];
    __shared__ float s_mu, s_rinv;
    const int lane = tid & 31, wrp = tid >> 5;
    if (lane == 0) { ws[wrp] = sum; wq[wrp] = sq; }
    __syncthreads();
    if (tid < 32) {
        float a  = (tid < 8) ? ws[tid] : 0.f;
        float b2 = (tid < 8) ? wq[tid] : 0.f;
#pragma unroll
        for (int off = 4; off > 0; off >>= 1) {
            a  += __shfl_xor_sync(0xffffffffu, a, off);
            b2 += __shfl_xor_sync(0xffffffffu, b2, off);
        }
        if (tid == 0) {
            float mu  = a * (1.0f / EE);
            float var = b2 * (1.0f / EE) - mu * mu;
            s_mu = mu;
            s_rinv = rsqrtf(var + LN_EPS);
        }
    }
    __syncthreads();
    const float mu = s_mu, rinv = s_rinv;
    float4 w4 = *(const float4*)(w + tid * 4);
    float4 b4 = *(const float4*)(bias + tid * 4);
    float4 o;
    o.x = (y0 - mu) * rinv * w4.x + b4.x;
    o.y = (y1 - mu) * rinv * w4.y + b4.y;
    o.z = (y2 - mu) * rinv * w4.z + b4.z;
    o.w = (y3 - mu) * rinv * w4.w + b4.w;
    *(float4*)(out + (size_t)token * EE + tid * 4) = o;
}

// ---------------------------------------------------------------------------
extern "C" void kernel_launch(void* const* d_in, const int* in_sizes, int n_in,
                              void* d_out, int out_size)
{
    const float* Wq = (const float*)d_in[0];
    const float* Wk = (const float*)d_in[1];
    const float* X  = (const float*)d_in[2];
    const float* lw = (const float*)d_in[3];
    const float* lb = (const float*)d_in[4];
    float* out = (float*)d_out;

    cudaFuncSetAttribute(gemm_qk_h,
                         cudaFuncAttributeMaxDynamicSharedMemorySize,
                         G_SMEM_BYTES);
    cudaFuncSetAttribute(attn_h,
                         cudaFuncAttributeMaxDynamicSharedMemorySize,
                         AT_SMEM_BYTES);

    wconv_kernel<<<dim3(1024, 2), 256>>>(Wq, Wk);
    vt_kernel<<<dim3(32, 64), 256>>>(X);
    gemm_qk_h<<<dim3(8, 64, 2), 256, G_SMEM_BYTES>>>();
    attn_h<<<dim3(16, 64), 256, AT_SMEM_BYTES>>>();
    ln_kernel<<<dim3(TOK), 256>>>(X, lw, lb, out);
}

// round 17
// speedup vs baseline: 1.1351x; 1.0207x over previous
#include <cuda_runtime.h>
#include <cuda_fp16.h>
#include <cstdint>
#include <math.h>

#define BB 4
#define SS 2048
#define EE 1024
#define HH 16
#define DD 64
#define TOK (BB * SS)
#define LN_EPS 1e-5f
// SCALE * log2(e): softmax done in exp2 domain
#define QSCALE 0.1803368801111244f

__device__ __half g_xh[(size_t)TOK * EE];            // fp16 copy of X
__device__ __half g_wh[2][(size_t)EE * EE];          // fp16 Wq, Wk
__device__ __half g_qh[(size_t)TOK * EE];
__device__ __half g_kh[(size_t)TOK * EE];
__device__ __half g_vt[(size_t)BB * HH * DD * SS];   // [b][h][d][s]
__device__ __half g_ctxh[(size_t)TOK * EE];          // fp16 context

// ---------------------------------------------------------------------------
// PTX helpers
// ---------------------------------------------------------------------------
__device__ __forceinline__ uint32_t smem_u32(const void* p) {
    uint32_t a;
    asm("{ .reg .u64 t; cvta.to.shared.u64 t, %1; cvt.u32.u64 %0, t; }"
        : "=r"(a) : "l"(p));
    return a;
}

#define CP_ASYNC16(sa, gp) \
    asm volatile("cp.async.cg.shared.global [%0], [%1], 16;" \
                 :: "r"(sa), "l"(gp))
#define CP_COMMIT() asm volatile("cp.async.commit_group;" ::: "memory")
#define CP_WAIT0()  asm volatile("cp.async.wait_group 0;" ::: "memory")

#define LDSM4(R0, R1, R2, R3, ADDR) \
    asm volatile("ldmatrix.sync.aligned.m8n8.x4.shared.b16 {%0,%1,%2,%3}, [%4];" \
                 : "=r"(R0), "=r"(R1), "=r"(R2), "=r"(R3) : "r"(ADDR))
#define LDSM4T(R0, R1, R2, R3, ADDR) \
    asm volatile("ldmatrix.sync.aligned.m8n8.x4.trans.shared.b16 {%0,%1,%2,%3}, [%4];" \
                 : "=r"(R0), "=r"(R1), "=r"(R2), "=r"(R3) : "r"(ADDR))

// fp32-accumulate mma (GEMM, PV, l)
#define MMA16816(D, A0, A1, A2, A3, B0, B1) \
    asm volatile("mma.sync.aligned.m16n8k16.row.col.f32.f16.f16.f32 " \
                 "{%0,%1,%2,%3}, {%4,%5,%6,%7}, {%8,%9}, {%0,%1,%2,%3};" \
                 : "+f"((D)[0]), "+f"((D)[1]), "+f"((D)[2]), "+f"((D)[3]) \
                 : "r"(A0), "r"(A1), "r"(A2), "r"(A3), "r"(B0), "r"(B1))

// fp16-accumulate mma (attention S): D regs come out in PV A-fragment layout
#define MMA16816_H(D0, D1, A0, A1, A2, A3, B0, B1) \
    asm volatile("mma.sync.aligned.m16n8k16.row.col.f16.f16.f16.f16 " \
                 "{%0,%1}, {%2,%3,%4,%5}, {%6,%7}, {%0,%1};" \
                 : "+r"(D0), "+r"(D1) \
                 : "r"(A0), "r"(A1), "r"(A2), "r"(A3), "r"(B0), "r"(B1))

// exp2 on packed fp16x2, in place
#define EX2H2(R) asm("ex2.approx.f16x2 %0, %0;" : "+r"(R))

#define ONES_H2 0x3C003C00u   // (1.0h, 1.0h)

__device__ __forceinline__ uint32_t pack_h2(float a, float b) {
    __half2 h = __floats2half2_rn(a, b);
    return *reinterpret_cast<uint32_t*>(&h);
}

// ---------------------------------------------------------------------------
// Kernel 0: X -> g_vt [b][h][d][s] fp16 AND g_xh row-major fp16,
// PLUS a 1024-float slice of Wq/Wk -> fp16 per block (replaces wconv).
// grid (32, 64), 256 thr.
// ---------------------------------------------------------------------------
__global__ __launch_bounds__(256) void vt_kernel(
    const float* __restrict__ X,
    const float* __restrict__ Wq,
    const float* __restrict__ Wk)
{
    __shared__ float sm[64][65];
    const int tid = threadIdx.x;
    const int bh = blockIdx.y, b = bh >> 4, h = bh & 15;
    const int s0 = blockIdx.x * 64;

    // W conversion slice: 2048 blocks x 1024 floats covers Wq then Wk.
    {
        const int slice = blockIdx.x + blockIdx.y * 32;      // 0..2047
        const float* wsrc = (slice < 1024) ? Wq : Wk;
        __half* wdst = g_wh[slice >> 10];
        const size_t off = (size_t)(slice & 1023) * 1024 + tid * 4;
        float4 v = *(const float4*)(wsrc + off);
        uint2 hx = make_uint2(pack_h2(v.x, v.y), pack_h2(v.z, v.w));
        *reinterpret_cast<uint2*>(wdst + off) = hx;
    }

#pragma unroll
    for (int r = 0; r < 4; ++r) {
        int idx = tid + r * 256;
        int row = idx >> 4;
        int c4  = (idx & 15) << 2;
        const size_t goff = ((size_t)(b * SS + s0 + row)) * EE + h * DD + c4;
        float4 v = *(const float4*)(X + goff);
        sm[row][c4 + 0] = v.x; sm[row][c4 + 1] = v.y;
        sm[row][c4 + 2] = v.z; sm[row][c4 + 3] = v.w;
        uint2 hx = make_uint2(pack_h2(v.x, v.y), pack_h2(v.z, v.w));
        *reinterpret_cast<uint2*>(g_xh + goff) = hx;
    }
    __syncthreads();
#pragma unroll
    for (int r = 0; r < 8; ++r) {
        int idx = tid + r * 256;
        int d  = idx >> 5;
        int s2 = (idx & 31) * 2;
        __half2 h2 = __floats2half2_rn(sm[s2][d], sm[s2 + 1][d]);
        *reinterpret_cast<__half2*>(g_vt + ((size_t)bh * DD + d) * SS + s0 + s2) = h2;
    }
}

// ---------------------------------------------------------------------------
// Kernel 1: split Q/K projection GEMM, fp16 mma, BK=64 chunks, 2-stage
// cp.async double buffer with ONE barrier per chunk (round-16 winner).
// ---------------------------------------------------------------------------
#define GA_PITCH 144
#define GB_PITCH 272
#define G_SA(buf) ((buf) * 18432)
#define G_SB(buf) (36864 + (buf) * 17408)
#define G_SMEM_BYTES (36864 + 2 * 17408)   // 71680

__global__ __launch_bounds__(256) void gemm_qk_h()
{
    extern __shared__ char smg[];
    const uint32_t sb = smem_u32(smg);

    const __half* Xh = g_xh;
    const __half* Wh = g_wh[blockIdx.z];
    __half* C        = (blockIdx.z == 0) ? g_qh : g_kh;
    const float qsc  = (blockIdx.z == 0) ? QSCALE : 1.0f;

    const int m0 = blockIdx.y * 128;
    const int n0 = blockIdx.x * 128;
    const int tid = threadIdx.x;
    const int wid = tid >> 5;
    const int lane = tid & 31;
    const int gid = lane >> 2;
    const int tig = lane & 3;
    const int wm = (wid >> 1) * 32;
    const int wn = (wid & 1) * 64;

    float acc[2][8][4];
#pragma unroll
    for (int mt = 0; mt < 2; ++mt)
#pragma unroll
        for (int nt = 0; nt < 8; ++nt)
#pragma unroll
            for (int r = 0; r < 4; ++r) acc[mt][nt][r] = 0.f;

#pragma unroll
    for (int i = 0; i < 4; ++i) {
        int idx = tid + i * 256;
        int arow = idx >> 3, aseg = idx & 7;
        CP_ASYNC16(sb + G_SA(0) + arow * GA_PITCH + aseg * 16,
                   Xh + (size_t)(m0 + arow) * EE + aseg * 8);
        int brow = idx >> 4, bseg = idx & 15;
        CP_ASYNC16(sb + G_SB(0) + brow * GB_PITCH + bseg * 16,
                   Wh + (size_t)brow * EE + n0 + bseg * 8);
    }
    CP_COMMIT();

    const uint32_t a_lm = (uint32_t)((lane & 15) * GA_PITCH + ((lane & 16) ? 16 : 0));
    const uint32_t b_lm = (uint32_t)((lane & 15) * GB_PITCH + ((lane & 16) ? 16 : 0));

    for (int ch = 0; ch < 16; ++ch) {
        const int buf = ch & 1;
        CP_WAIT0();
        __syncthreads();

        if (ch + 1 < 16) {
            const int k0 = (ch + 1) * 64;
            const int nb = buf ^ 1;
#pragma unroll
            for (int i = 0; i < 4; ++i) {
                int idx = tid + i * 256;
                int arow = idx >> 3, aseg = idx & 7;
                CP_ASYNC16(sb + G_SA(nb) + arow * GA_PITCH + aseg * 16,
                           Xh + (size_t)(m0 + arow) * EE + k0 + aseg * 8);
                int brow = idx >> 4, bseg = idx & 15;
                CP_ASYNC16(sb + G_SB(nb) + brow * GB_PITCH + bseg * 16,
                           Wh + (size_t)(k0 + brow) * EE + n0 + bseg * 8);
            }
            CP_COMMIT();
        }

        const uint32_t sa  = sb + G_SA(buf);
        const uint32_t sbf = sb + G_SB(buf);

#pragma unroll
        for (int ks = 0; ks < 4; ++ks) {
            uint32_t af[2][4];
#pragma unroll
            for (int mt = 0; mt < 2; ++mt) {
                LDSM4(af[mt][0], af[mt][1], af[mt][2], af[mt][3],
                      sa + (wm + mt * 16) * GA_PITCH + a_lm + ks * 32);
            }
#pragma unroll
            for (int np = 0; np < 4; ++np) {
                uint32_t b0, b1, b2, b3;
                LDSM4T(b0, b1, b2, b3,
                       sbf + ks * 16 * GB_PITCH + b_lm + (wn + np * 16) * 2);
                MMA16816(acc[0][2 * np + 0], af[0][0], af[0][1], af[0][2], af[0][3], b0, b1);
                MMA16816(acc[0][2 * np + 1], af[0][0], af[0][1], af[0][2], af[0][3], b2, b3);
                MMA16816(acc[1][2 * np + 0], af[1][0], af[1][1], af[1][2], af[1][3], b0, b1);
                MMA16816(acc[1][2 * np + 1], af[1][0], af[1][1], af[1][2], af[1][3], b2, b3);
            }
        }
    }

#pragma unroll
    for (int mt = 0; mt < 2; ++mt) {
        const int r0 = m0 + wm + mt * 16 + gid;
#pragma unroll
        for (int nt = 0; nt < 8; ++nt) {
            const int ncol = n0 + wn + nt * 8 + tig * 2;
            __half2 h0 = __floats2half2_rn(acc[mt][nt][0] * qsc, acc[mt][nt][1] * qsc);
            __half2 h1 = __floats2half2_rn(acc[mt][nt][2] * qsc, acc[mt][nt][3] * qsc);
            *reinterpret_cast<__half2*>(C + (size_t)(r0 + 0) * EE + ncol) = h0;
            *reinterpret_cast<__half2*>(C + (size_t)(r0 + 8) * EE + ncol) = h1;
        }
    }
}

// ---------------------------------------------------------------------------
// Kernel 2: flash attention (round-16 winner), fp16 context output.
// ---------------------------------------------------------------------------
#define AT_OQ    0
#define AT_OK    18432
#define AT_KBUF  18432
#define AT_OV    (18432 + 2 * 18432)        // 55296
#define AT_VBUF  17408
#define AT_SMEM_BYTES (AT_OV + 2 * AT_VBUF) // 90112

__global__ __launch_bounds__(256, 2) void attn_h()
{
    extern __shared__ char sma[];
    const uint32_t sb = smem_u32(sma);
    const int tid = threadIdx.x;
    const int wid = tid >> 5, lane = tid & 31;
    const int gid = lane >> 2, tig = lane & 3;
    const int wm = wid * 16;
    const int bh = blockIdx.y, b = bh >> 4, h = bh & 15;
    const int s0 = blockIdx.x * 128;

    const __half* qsrc = g_qh + ((size_t)(b * SS + s0)) * EE + h * DD;
    const __half* ksrc = g_kh + ((size_t)b * SS) * EE + h * DD;
    const __half* vsrc = g_vt + ((size_t)bh * DD) * SS;

#pragma unroll
    for (int r = 0; r < 4; ++r) {
        int idx = tid + r * 256;
        int row = idx >> 3, seg = idx & 7;
        CP_ASYNC16(sb + AT_OQ + row * 144 + seg * 16,
                   qsrc + (size_t)row * EE + seg * 8);
    }
#pragma unroll
    for (int r = 0; r < 4; ++r) {
        int idx = tid + r * 256;
        int krow = idx >> 3, kseg = idx & 7;
        CP_ASYNC16(sb + AT_OK + krow * 144 + kseg * 16,
                   ksrc + (size_t)krow * EE + kseg * 8);
        int vrow = idx >> 4, vseg = idx & 15;
        CP_ASYNC16(sb + AT_OV + vrow * 272 + vseg * 16,
                   vsrc + (size_t)vrow * SS + vseg * 8);
    }
    CP_COMMIT();
    CP_WAIT0();
    __syncthreads();

    uint32_t qf[4][4];
    {
        const uint32_t qoff = sb + AT_OQ + (uint32_t)(wm + (lane & 15)) * 144
                              + ((lane & 16) ? 16u : 0u);
#pragma unroll
        for (int ks = 0; ks < 4; ++ks)
            LDSM4(qf[ks][0], qf[ks][1], qf[ks][2], qf[ks][3], qoff + 32 * ks);
    }

    float oacc[8][4];
#pragma unroll
    for (int nt = 0; nt < 8; ++nt)
#pragma unroll
        for (int r = 0; r < 4; ++r) oacc[nt][r] = 0.f;
    float lacc[4]  = {0.f, 0.f, 0.f, 0.f};
    float lacc2[4] = {0.f, 0.f, 0.f, 0.f};

    const uint32_t kmoff = (uint32_t)((lane & 7) * 144 + (lane >> 3) * 16);
    const uint32_t vmoff = (uint32_t)((lane & 7) * 272 + (lane >> 3) * 16);

    for (int kt = 0; kt < 16; ++kt) {
        const int buf = kt & 1;
        if (kt > 0) {
            CP_WAIT0();
            __syncthreads();
        }
        if (kt + 1 < 16) {
            const int t0n = (kt + 1) * 128;
            const int nb = buf ^ 1;
#pragma unroll
            for (int r = 0; r < 4; ++r) {
                int idx = tid + r * 256;
                int krow = idx >> 3, kseg = idx & 7;
                CP_ASYNC16(sb + AT_OK + nb * AT_KBUF + krow * 144 + kseg * 16,
                           ksrc + (size_t)(t0n + krow) * EE + kseg * 8);
                int vrow = idx >> 4, vseg = idx & 15;
                CP_ASYNC16(sb + AT_OV + nb * AT_VBUF + vrow * 272 + vseg * 16,
                           vsrc + (size_t)vrow * SS + t0n + vseg * 8);
            }
            CP_COMMIT();
        }

        const uint32_t kb = sb + AT_OK + buf * AT_KBUF + kmoff;
        const uint32_t vb = sb + AT_OV + buf * AT_VBUF + vmoff;

#pragma unroll
        for (int c = 0; c < 4; ++c) {
            uint32_t sh[4][2];
#pragma unroll
            for (int nt = 0; nt < 4; ++nt) { sh[nt][0] = 0u; sh[nt][1] = 0u; }

#pragma unroll
            for (int nt = 0; nt < 4; ++nt) {
                const int ntg = c * 4 + nt;
                uint32_t k0, k1, k2, k3, k4, k5, k6, k7;
                LDSM4(k0, k1, k2, k3, kb + ntg * 1152);
                LDSM4(k4, k5, k6, k7, kb + ntg * 1152 + 64);
                MMA16816_H(sh[nt][0], sh[nt][1], qf[0][0], qf[0][1], qf[0][2], qf[0][3], k0, k1);
                MMA16816_H(sh[nt][0], sh[nt][1], qf[1][0], qf[1][1], qf[1][2], qf[1][3], k2, k3);
                MMA16816_H(sh[nt][0], sh[nt][1], qf[2][0], qf[2][1], qf[2][2], qf[2][3], k4, k5);
                MMA16816_H(sh[nt][0], sh[nt][1], qf[3][0], qf[3][1], qf[3][2], qf[3][3], k6, k7);
            }

#pragma unroll
            for (int nt = 0; nt < 4; ++nt) { EX2H2(sh[nt][0]); EX2H2(sh[nt][1]); }

            MMA16816(lacc,  sh[0][0], sh[0][1], sh[1][0], sh[1][1], ONES_H2, ONES_H2);
            MMA16816(lacc2, sh[2][0], sh[2][1], sh[3][0], sh[3][1], ONES_H2, ONES_H2);

#pragma unroll
            for (int nt = 0; nt < 8; ++nt) {
                uint32_t v0, v1, v2, v3;
                LDSM4(v0, v1, v2, v3, vb + nt * 2176 + c * 64);
                MMA16816(oacc[nt], sh[0][0], sh[0][1], sh[1][0], sh[1][1], v0, v1);
                MMA16816(oacc[nt], sh[2][0], sh[2][1], sh[3][0], sh[3][1], v2, v3);
            }
        }
    }

    const float li0 = 1.0f / (lacc[0] + lacc2[0]);
    const float li1 = 1.0f / (lacc[2] + lacc2[2]);

    __half* op = g_ctxh + ((size_t)(b * SS + s0 + wm + gid)) * EE + h * DD;
#pragma unroll
    for (int nt = 0; nt < 8; ++nt) {
        const int dcol = nt * 8 + tig * 2;
        uint32_t h0 = pack_h2(oacc[nt][0] * li0, oacc[nt][1] * li0);
        uint32_t h1 = pack_h2(oacc[nt][2] * li1, oacc[nt][3] * li1);
        *reinterpret_cast<uint32_t*>(op + dcol) = h0;
        *reinterpret_cast<uint32_t*>(op + (size_t)8 * EE + dcol) = h1;
    }
}

// ---------------------------------------------------------------------------
// Kernel 3: residual + LayerNorm; context read as fp16.
// ---------------------------------------------------------------------------
__global__ __launch_bounds__(256) void ln_kernel(
    const float* __restrict__ X,
    const float* __restrict__ w,
    const float* __restrict__ bias,
    float* __restrict__ out)
{
    const int token = blockIdx.x;
    const int tid = threadIdx.x;
    const __half* cp = g_ctxh + (size_t)token * EE;
    const float* xp = X + (size_t)token * EE;

    uint2 craw = *(const uint2*)(cp + tid * 4);
    __half2 ch0 = *reinterpret_cast<__half2*>(&craw.x);
    __half2 ch1 = *reinterpret_cast<__half2*>(&craw.y);
    float2 c01 = __half22float2(ch0);
    float2 c23 = __half22float2(ch1);
    float4 xv = *(const float4*)(xp + tid * 4);
    float y0 = c01.x + xv.x, y1 = c01.y + xv.y;
    float y2 = c23.x + xv.z, y3 = c23.y + xv.w;

    float sum = y0 + y1 + y2 + y3;
    float sq  = y0 * y0 + y1 * y1 + y2 * y2 + y3 * y3;
#pragma unroll
    for (int off = 16; off > 0; off >>= 1) {
        sum += __shfl_xor_sync(0xffffffffu, sum, off);
        sq  += __shfl_xor_sync(0xffffffffu, sq,  off);
    }
    __shared__ float ws[8], wq[8];
    __shared__ float s_mu, s_rinv;
    const int lane = tid & 31, wrp = tid >> 5;
    if (lane == 0) { ws[wrp] = sum; wq[wrp] = sq; }
    __syncthreads();
    if (tid < 32) {
        float a  = (tid < 8) ? ws[tid] : 0.f;
        float b2 = (tid < 8) ? wq[tid] : 0.f;
#pragma unroll
        for (int off = 4; off > 0; off >>= 1) {
            a  += __shfl_xor_sync(0xffffffffu, a, off);
            b2 += __shfl_xor_sync(0xffffffffu, b2, off);
        }
        if (tid == 0) {
            float mu  = a * (1.0f / EE);
            float var = b2 * (1.0f / EE) - mu * mu;
            s_mu = mu;
            s_rinv = rsqrtf(var + LN_EPS);
        }
    }
    __syncthreads();
    const float mu = s_mu, rinv = s_rinv;
    float4 w4 = *(const float4*)(w + tid * 4);
    float4 b4 = *(const float4*)(bias + tid * 4);
    float4 o;
    o.x = (y0 - mu) * rinv * w4.x + b4.x;
    o.y = (y1 - mu) * rinv * w4.y + b4.y;
    o.z = (y2 - mu) * rinv * w4.z + b4.z;
    o.w = (y3 - mu) * rinv * w4.w + b4.w;
    *(float4*)(out + (size_t)token * EE + tid * 4) = o;
}

// ---------------------------------------------------------------------------
extern "C" void kernel_launch(void* const* d_in, const int* in_sizes, int n_in,
                              void* d_out, int out_size)
{
    const float* Wq = (const float*)d_in[0];
    const float* Wk = (const float*)d_in[1];
    const float* X  = (const float*)d_in[2];
    const float* lw = (const float*)d_in[3];
    const float* lb = (const float*)d_in[4];
    float* out = (float*)d_out;

    cudaFuncSetAttribute(gemm_qk_h,
                         cudaFuncAttributeMaxDynamicSharedMemorySize,
                         G_SMEM_BYTES);
    cudaFuncSetAttribute(attn_h,
                         cudaFuncAttributeMaxDynamicSharedMemorySize,
                         AT_SMEM_BYTES);

    vt_kernel<<<dim3(32, 64), 256>>>(X, Wq, Wk);
    gemm_qk_h<<<dim3(8, 64, 2), 256, G_SMEM_BYTES>>>();
    attn_h<<<dim3(16, 64), 256, AT_SMEM_BYTES>>>();
    ln_kernel<<<dim3(TOK), 256>>>(X, lw, lb, out);
}